// round 8
// baseline (speedup 1.0000x reference)
#include <cuda_runtime.h>
#include <cuda_bf16.h>
#include <cstdint>

#define BB   16
#define NN   8192
#define KNB  16
#define MTOT (BB*NN)      // 131072
#define H3   64
#define H2   128
#define H1   512
#define EPSBN 1e-5f

typedef unsigned long long ull;
typedef unsigned int uint;

// ---------------- scratch ----------------
__device__ float g_pre1[MTOT*H3];
__device__ float g_pre2[MTOT*H2];
__device__ unsigned short g_w1hi[H2*H3];  // [col][k] bf16 hi of gc1_w^T (128x64)
__device__ unsigned short g_w1lo[H2*H3];
__device__ unsigned short g_w2hi[H1*H2];  // [col][k] bf16 hi of gc2_w^T (512x128)
__device__ unsigned short g_w2lo[H1*H2];
__device__ float g_sum1[H3], g_sq1[H3];
__device__ float g_sum2[H2], g_sq2[H2];
__device__ float g_sum3[H1], g_sq3[H1];
__device__ uint  g_maxk[BB*H1], g_mink[BB*H1];
__device__ float g_pool[BB*H1];
__device__ float g_pre4[BB*H1];
__device__ float g_dc1[BB*3], g_dc2[BB*3];
__device__ float g_d1p[6];
__device__ float g_sumd[3], g_sqd[3];

// ---------------- helpers ----------------
__device__ __forceinline__ uint fkey(float f){
    uint u = __float_as_uint(f);
    return (u & 0x80000000u) ? ~u : (u | 0x80000000u);
}
__device__ __forceinline__ float keyf(uint k){
    uint u = (k & 0x80000000u) ? (k ^ 0x80000000u) : ~k;
    return __uint_as_float(u);
}
__device__ __forceinline__ uint smem_u32(const void* p){
    uint a; asm("{ .reg .u64 t; cvta.to.shared.u64 t, %1; cvt.u32.u64 %0, t; }" : "=r"(a) : "l"(p)); return a;
}
__device__ __forceinline__ uint pbf2(float a, float b){
    __nv_bfloat162 h = __floats2bfloat162_rn(a, b);
    return *(uint*)&h;
}
__device__ __forceinline__ void ldm4(uint* r, uint addr){
    asm volatile("ldmatrix.sync.aligned.m8n8.x4.shared.b16 {%0,%1,%2,%3}, [%4];"
        : "=r"(r[0]),"=r"(r[1]),"=r"(r[2]),"=r"(r[3]) : "r"(addr));
}
__device__ __forceinline__ void mma16816(float* d, const uint* a, uint b0, uint b1){
    asm volatile("mma.sync.aligned.m16n8k16.row.col.f32.bf16.bf16.f32 "
        "{%0,%1,%2,%3}, {%4,%5,%6,%7}, {%8,%9}, {%0,%1,%2,%3};"
        : "+f"(d[0]),"+f"(d[1]),"+f"(d[2]),"+f"(d[3])
        : "r"(a[0]),"r"(a[1]),"r"(a[2]),"r"(a[3]), "r"(b0),"r"(b1));
}

// gather 17 rows (self+16 nbrs) of 16 channels with BN+ReLU, /17, split bf16 hi/lo into smem
template<int CPF4>  // float4 per row = C/4
__device__ __forceinline__ void gather_split(
    const float* __restrict__ pre, const int* knn_s, const float* bns, const float* bnh,
    int node, int cq, int gi, int base, char* sm, uint ahOff, uint alOff, uint stride)
{
    float4 sc4[4], sh4[4];
    #pragma unroll
    for (int j=0;j<4;j++){
        sc4[j] = ((const float4*)bns)[(cq>>2)+j];
        sh4[j] = ((const float4*)bnh)[(cq>>2)+j];
    }
    float a[16];
    {
        const float4* rp = (const float4*)(pre + (size_t)gi*(CPF4*4) + cq);
        #pragma unroll
        for (int j=0;j<4;j++){
            float4 v = rp[j];
            a[4*j+0] = fmaxf(fmaf(v.x, sc4[j].x, sh4[j].x), 0.f);
            a[4*j+1] = fmaxf(fmaf(v.y, sc4[j].y, sh4[j].y), 0.f);
            a[4*j+2] = fmaxf(fmaf(v.z, sc4[j].z, sh4[j].z), 0.f);
            a[4*j+3] = fmaxf(fmaf(v.w, sc4[j].w, sh4[j].w), 0.f);
        }
    }
    #pragma unroll
    for (int k=0;k<KNB;k++){
        int nb = base + knn_s[node*KNB + k];
        const float4* rp = (const float4*)(pre + (size_t)nb*(CPF4*4) + cq);
        #pragma unroll
        for (int j=0;j<4;j++){
            float4 v = rp[j];
            a[4*j+0] += fmaxf(fmaf(v.x, sc4[j].x, sh4[j].x), 0.f);
            a[4*j+1] += fmaxf(fmaf(v.y, sc4[j].y, sh4[j].y), 0.f);
            a[4*j+2] += fmaxf(fmaf(v.z, sc4[j].z, sh4[j].z), 0.f);
            a[4*j+3] += fmaxf(fmaf(v.w, sc4[j].w, sh4[j].w), 0.f);
        }
    }
    const float s = 1.f/17.f;
    uint hi[8], lo[8];
    #pragma unroll
    for (int j=0;j<8;j++){
        float x = a[2*j]*s, y = a[2*j+1]*s;
        __nv_bfloat162 h = __floats2bfloat162_rn(x, y);
        hi[j] = *(uint*)&h;
        lo[j] = pbf2(x - __bfloat162float(h.x), y - __bfloat162float(h.y));
    }
    uint dof = node*stride + (cq>>4)*32;
    *(uint4*)(sm + ahOff + dof)      = make_uint4(hi[0],hi[1],hi[2],hi[3]);
    *(uint4*)(sm + ahOff + dof + 16) = make_uint4(hi[4],hi[5],hi[6],hi[7]);
    *(uint4*)(sm + alOff + dof)      = make_uint4(lo[0],lo[1],lo[2],lo[3]);
    *(uint4*)(sm + alOff + dof + 16) = make_uint4(lo[4],lo[5],lo[6],lo[7]);
}

// ---------------- init: zero stats + split both weight matrices ----------------
__global__ void k_init(const float* __restrict__ w1, const float* __restrict__ w2){
    int i = blockIdx.x*blockDim.x + threadIdx.x;   // 0..65535
    if (i < H1*H2){
        int c = i >> 7, k = i & 127;
        float v = w2[(size_t)k*H1 + c];
        __nv_bfloat16 h = __float2bfloat16_rn(v);
        float r = v - __bfloat162float(h);
        __nv_bfloat16 l = __float2bfloat16_rn(r);
        g_w2hi[i] = *(unsigned short*)&h;
        g_w2lo[i] = *(unsigned short*)&l;
    }
    if (i < H2*H3){
        int c = i >> 6, k = i & 63;
        float v = w1[(size_t)k*H2 + c];
        __nv_bfloat16 h = __float2bfloat16_rn(v);
        float r = v - __bfloat162float(h);
        __nv_bfloat16 l = __float2bfloat16_rn(r);
        g_w1hi[i] = *(unsigned short*)&h;
        g_w1lo[i] = *(unsigned short*)&l;
    }
    if (i < BB*H1){ g_maxk[i]=0u; g_mink[i]=0xFFFFFFFFu; }
    if (i < H1){ g_sum3[i]=0.f; g_sq3[i]=0.f; }
    if (i < H2){ g_sum2[i]=0.f; g_sq2[i]=0.f; }
    if (i < H3){ g_sum1[i]=0.f; g_sq1[i]=0.f; }
    if (i < 3){ g_sumd[i]=0.f; g_sqd[i]=0.f; }
}

// covariance features + Linear(12,64) + BN stats
__global__ __launch_bounds__(256) void k_cov_e1(
    const float* __restrict__ data, const int* __restrict__ knn,
    const float* __restrict__ w, const float* __restrict__ bias)
{
    __shared__ float Ws[12*H3];
    __shared__ float bs[H3];
    __shared__ float x0s[256*12];
    __shared__ float ssum[H3], ssq[H3];
    int t = threadIdx.x;
    for (int i = t; i < 12*H3; i += 256) Ws[i] = w[i];
    if (t < H3){ bs[t] = bias[t]; ssum[t]=0.f; ssq[t]=0.f; }

    int gi = blockIdx.x*256 + t;
    int b = gi >> 13;
    const int* kp = knn + (size_t)gi*KNB;
    float sx=0,sy=0,sz=0,sxx=0,sxy=0,sxz=0,syy=0,syz=0,szz=0;
    #pragma unroll
    for (int k=0;k<KNB;k++){
        int j = kp[k];
        const float* p = data + ((size_t)(b*NN + j))*3;
        float x=p[0], y=p[1], z=p[2];
        sx+=x; sy+=y; sz+=z;
        sxx+=x*x; sxy+=x*y; sxz+=x*z; syy+=y*y; syz+=y*z; szz+=z*z;
    }
    float mx=sx*(1.f/16.f), my=sy*(1.f/16.f), mz=sz*(1.f/16.f);
    const float i15 = 1.f/15.f;
    float cxx=(sxx-16.f*mx*mx)*i15, cxy=(sxy-16.f*mx*my)*i15, cxz=(sxz-16.f*mx*mz)*i15;
    float cyy=(syy-16.f*my*my)*i15, cyz=(syz-16.f*my*mz)*i15, czz=(szz-16.f*mz*mz)*i15;
    float* xr = &x0s[t*12];
    xr[0]=data[(size_t)gi*3+0]; xr[1]=data[(size_t)gi*3+1]; xr[2]=data[(size_t)gi*3+2];
    xr[3]=cxx; xr[4]=cxy; xr[5]=cxz; xr[6]=cxy; xr[7]=cyy; xr[8]=cyz; xr[9]=cxz; xr[10]=cyz; xr[11]=czz;
    __syncthreads();

    int c = t & 63;
    float bsum=0.f, bsq=0.f;
    float* outp = g_pre1 + (size_t)blockIdx.x*256*H3;
    #pragma unroll 4
    for (int kq=0;kq<64;kq++){
        int e = t + kq*256;
        const float* x0 = &x0s[(e>>6)*12];
        float v = bs[c];
        #pragma unroll
        for (int j=0;j<12;j++) v = fmaf(x0[j], Ws[j*H3+c], v);
        outp[e] = v;
        bsum += v; bsq += v*v;
    }
    atomicAdd(&ssum[c], bsum); atomicAdd(&ssq[c], bsq);
    __syncthreads();
    if (t < H3){ atomicAdd(&g_sum1[t], ssum[t]); atomicAdd(&g_sq1[t], ssq[t]); }
}

// ---------------- gemm1f: fused bn1 + gather + 3-term bf16 HMMA (128n x 128c, K=64) ----------------
#define G1_KNN 0u
#define G1_BNS 8192u
#define G1_BNH 8448u
#define G1_AH  8704u
#define G1_AL  27136u
#define G1_BH  45568u
#define G1_BL  64000u
#define G1_SUM 82432u
#define G1_SQ  82944u
#define G1_SMEM 83456

__global__ void __launch_bounds__(256, 2) k_gemm1f(
    const int* __restrict__ knn, const float* __restrict__ eg, const float* __restrict__ ebe)
{
    extern __shared__ __align__(16) char sm[];
    uint sb = smem_u32(sm);
    int t = threadIdx.x, lane = t & 31, wid = t >> 5;
    int node0 = blockIdx.x*128;

    int* knn_s = (int*)(sm + G1_KNN);
    float* bns = (float*)(sm + G1_BNS);
    float* bnh = (float*)(sm + G1_BNH);
    float* ssum = (float*)(sm + G1_SUM);
    float* ssq  = (float*)(sm + G1_SQ);

    // bn1 inline
    if (t < H3){
        float invM = 1.f/(float)MTOT;
        float m = g_sum1[t]*invM;
        float v = fmaxf(g_sq1[t]*invM - m*m, 0.f);
        float sc = eg[t]*rsqrtf(v+EPSBN);
        bns[t] = sc; bnh[t] = fmaf(-m, sc, ebe[t]);
    }
    if (t < 128){ ssum[t]=0.f; ssq[t]=0.f; }
    // knn for 128 nodes
    #pragma unroll
    for (int i=0;i<8;i++) knn_s[t + i*256] = knn[(size_t)node0*KNB + t + i*256];
    // B load (w1 hi/lo: 128 cols x 128B, stride 144)
    {
        int col = t >> 1, half = t & 1;
        const uint4* ph = (const uint4*)((const char*)g_w1hi + (size_t)col*128) + half*4;
        const uint4* pl = (const uint4*)((const char*)g_w1lo + (size_t)col*128) + half*4;
        uint4* dh = (uint4*)(sm + G1_BH + col*144 + half*64);
        uint4* dl = (uint4*)(sm + G1_BL + col*144 + half*64);
        #pragma unroll
        for (int i=0;i<4;i++){ dh[i] = ph[i]; dl[i] = pl[i]; }
    }
    __syncthreads();

    // gather: 2 passes x (64 nodes x 4 threads, 16 ch each)
    #pragma unroll
    for (int pass=0; pass<2; pass++){
        int node = pass*64 + (t >> 2);
        int cq = (t & 3)*16;
        int gi = node0 + node;
        int base = (gi >> 13)*NN;
        gather_split<16>(g_pre1, knn_s, bns, bnh, node, cq, gi, base, sm, G1_AH, G1_AL, 144u);
    }
    __syncthreads();

    // MMA phase
    int wm = wid >> 2, wn = wid & 3;
    uint aBase = sb + G1_AH + (uint)((wm*64 + (lane & 15))*144 + (lane >> 4)*16);
    uint bBase = sb + G1_BH + (uint)((wn*32 + (lane & 7) + ((lane >> 4) & 1)*8)*144 + ((lane >> 3) & 1)*16);

    float acc[4][4][4];
    #pragma unroll
    for (int mi=0;mi<4;mi++)
        #pragma unroll
        for (int j=0;j<4;j++)
            #pragma unroll
            for (int r=0;r<4;r++) acc[mi][j][r] = 0.f;

    #pragma unroll
    for (int ks=0; ks<4; ks++){
        uint bh[8], bl[8];
        ldm4(bh,   bBase + ks*32);
        ldm4(bh+4, bBase + 16*144 + ks*32);
        ldm4(bl,   bBase + (G1_BL-G1_BH) + ks*32);
        ldm4(bl+4, bBase + (G1_BL-G1_BH) + 16*144 + ks*32);
        #pragma unroll
        for (int mi=0; mi<4; mi++){
            uint ah[4], al[4];
            ldm4(ah, aBase + mi*16*144 + ks*32);
            ldm4(al, aBase + (G1_AL-G1_AH) + mi*16*144 + ks*32);
            #pragma unroll
            for (int j=0;j<4;j++){
                mma16816(acc[mi][j], ah, bh[2*j], bh[2*j+1]);
                mma16816(acc[mi][j], al, bh[2*j], bh[2*j+1]);
                mma16816(acc[mi][j], ah, bl[2*j], bl[2*j+1]);
            }
        }
    }

    // write pre2 + stats
    #pragma unroll
    for (int mi=0;mi<4;mi++){
        int r0 = node0 + wm*64 + mi*16 + (lane >> 2);
        #pragma unroll
        for (int j=0;j<4;j++){
            int c0 = wn*32 + j*8 + (lane & 3)*2;
            *(float2*)&g_pre2[(size_t)r0*H2 + c0]     = make_float2(acc[mi][j][0], acc[mi][j][1]);
            *(float2*)&g_pre2[(size_t)(r0+8)*H2 + c0] = make_float2(acc[mi][j][2], acc[mi][j][3]);
        }
    }
    #pragma unroll
    for (int j=0;j<4;j++){
        #pragma unroll
        for (int p=0;p<2;p++){
            float s=0.f, qq=0.f;
            #pragma unroll
            for (int mi=0;mi<4;mi++){
                #pragma unroll
                for (int r=0;r<2;r++){
                    float v = acc[mi][j][2*r+p];
                    s += v; qq = fmaf(v, v, qq);
                }
            }
            #pragma unroll
            for (int o=4;o<32;o<<=1){
                s  += __shfl_xor_sync(0xffffffffu, s, o);
                qq += __shfl_xor_sync(0xffffffffu, qq, o);
            }
            if (lane < 4){
                int colq = wn*32 + j*8 + lane*2 + p;
                atomicAdd(&ssum[colq], s);
                atomicAdd(&ssq[colq], qq);
            }
        }
    }
    __syncthreads();
    if (t < 128){
        atomicAdd(&g_sum2[t], ssum[t]);
        atomicAdd(&g_sq2[t], ssq[t]);
    }
}

// ---------------- gemm2f: fused bn2 + gather + 3-term bf16 HMMA (128n x 512c, K=128) ----------------
#define G2_KNN 0u
#define G2_BNS 8192u
#define G2_BNH 8704u
#define G2_AH  9216u
#define G2_AL  44032u
#define G2_BH  78848u
#define G2_BL  113664u
#define G2_SUM 148480u
#define G2_SQ  148992u
#define G2_MX  149504u
#define G2_MN  150016u
#define G2_SMEM 150528

__global__ void __launch_bounds__(512, 1) k_gemm2f(
    const int* __restrict__ knn, const float* __restrict__ gg, const float* __restrict__ gbe)
{
    extern __shared__ __align__(16) char sm[];
    uint sb = smem_u32(sm);
    int t = threadIdx.x, lane = t & 31, wid = t >> 5;
    int node0 = blockIdx.x*128;
    int batch = blockIdx.x >> 6;

    int* knn_s = (int*)(sm + G2_KNN);
    float* bns = (float*)(sm + G2_BNS);
    float* bnh = (float*)(sm + G2_BNH);
    float* ssum = (float*)(sm + G2_SUM);
    float* ssq  = (float*)(sm + G2_SQ);
    uint*  smx  = (uint*)(sm + G2_MX);
    uint*  smn  = (uint*)(sm + G2_MN);

    // bn2 inline
    if (t < H2){
        float invM = 1.f/(float)MTOT;
        float m = g_sum2[t]*invM;
        float v = fmaxf(g_sq2[t]*invM - m*m, 0.f);
        float sc = gg[t]*rsqrtf(v+EPSBN);
        bns[t] = sc; bnh[t] = fmaf(-m, sc, gbe[t]);
    }
    // knn
    #pragma unroll
    for (int i=0;i<4;i++) knn_s[t + i*512] = knn[(size_t)node0*KNB + t + i*512];
    __syncthreads();

    // gather: 2 passes x (64 nodes x 8 threads, 16 ch each)
    #pragma unroll
    for (int pass=0; pass<2; pass++){
        int node = pass*64 + (t >> 3);
        int cq = (t & 7)*16;
        int gi = node0 + node;
        int base = (gi >> 13)*NN;
        gather_split<32>(g_pre2, knn_s, bns, bnh, node, cq, gi, base, sm, G2_AH, G2_AL, 272u);
    }

    int wm = wid >> 2, wn = wid & 3;   // wm 0..3 (32 rows each), wn 0..3 (32 cols of quarter)
    uint aBase = sb + G2_AH + (uint)((wm*32 + (lane & 15))*272 + (lane >> 4)*16);
    uint bBase = sb + G2_BH + (uint)((wn*32 + (lane & 7) + ((lane >> 4) & 1)*8)*272 + ((lane >> 3) & 1)*16);

    for (int q = 0; q < 4; q++){
        int cb = q*128;
        // load B quarter (128 cols x 256B hi/lo, stride 272)
        {
            int col = t >> 2, q4 = t & 3;
            const uint4* ph = (const uint4*)((const char*)g_w2hi + (size_t)(cb+col)*256 + q4*64);
            const uint4* pl = (const uint4*)((const char*)g_w2lo + (size_t)(cb+col)*256 + q4*64);
            uint4* dh = (uint4*)(sm + G2_BH + col*272 + q4*64);
            uint4* dl = (uint4*)(sm + G2_BL + col*272 + q4*64);
            #pragma unroll
            for (int i=0;i<4;i++){ dh[i] = ph[i]; dl[i] = pl[i]; }
        }
        if (t < 128){ ssum[t]=0.f; ssq[t]=0.f; smx[t]=0u; smn[t]=0xFFFFFFFFu; }
        __syncthreads();

        float acc[2][4][4];
        #pragma unroll
        for (int mi=0;mi<2;mi++)
            #pragma unroll
            for (int j=0;j<4;j++)
                #pragma unroll
                for (int r=0;r<4;r++) acc[mi][j][r] = 0.f;

        #pragma unroll
        for (int ks=0; ks<8; ks++){
            uint bh[8], bl[8];
            ldm4(bh,   bBase + ks*32);
            ldm4(bh+4, bBase + 16*272 + ks*32);
            ldm4(bl,   bBase + (G2_BL-G2_BH) + ks*32);
            ldm4(bl+4, bBase + (G2_BL-G2_BH) + 16*272 + ks*32);
            #pragma unroll
            for (int mi=0; mi<2; mi++){
                uint ah[4], al[4];
                ldm4(ah, aBase + mi*16*272 + ks*32);
                ldm4(al, aBase + (G2_AL-G2_AH) + mi*16*272 + ks*32);
                #pragma unroll
                for (int j=0;j<4;j++){
                    mma16816(acc[mi][j], ah, bh[2*j], bh[2*j+1]);
                    mma16816(acc[mi][j], al, bh[2*j], bh[2*j+1]);
                    mma16816(acc[mi][j], ah, bl[2*j], bl[2*j+1]);
                }
            }
        }

        // per-column stats
        #pragma unroll
        for (int j=0;j<4;j++){
            #pragma unroll
            for (int p=0;p<2;p++){
                float s=0.f, qq=0.f, mx=-3.402823466e38f, mn=3.402823466e38f;
                #pragma unroll
                for (int mi=0;mi<2;mi++){
                    #pragma unroll
                    for (int r=0;r<2;r++){
                        float v = acc[mi][j][2*r+p];
                        s += v; qq = fmaf(v, v, qq);
                        mx = fmaxf(mx, v); mn = fminf(mn, v);
                    }
                }
                #pragma unroll
                for (int o=4;o<32;o<<=1){
                    s  += __shfl_xor_sync(0xffffffffu, s, o);
                    qq += __shfl_xor_sync(0xffffffffu, qq, o);
                    mx = fmaxf(mx, __shfl_xor_sync(0xffffffffu, mx, o));
                    mn = fminf(mn, __shfl_xor_sync(0xffffffffu, mn, o));
                }
                if (lane < 4){
                    int colq = wn*32 + j*8 + lane*2 + p;
                    atomicAdd(&ssum[colq], s);
                    atomicAdd(&ssq[colq], qq);
                    atomicMax(&smx[colq], fkey(mx));
                    atomicMin(&smn[colq], fkey(mn));
                }
            }
        }
        __syncthreads();
        if (t < 128){
            atomicAdd(&g_sum3[cb+t], ssum[t]);
            atomicAdd(&g_sq3[cb+t], ssq[t]);
            atomicMax(&g_maxk[batch*H1 + cb + t], smx[t]);
            atomicMin(&g_mink[batch*H1 + cb + t], smn[t]);
        }
        __syncthreads();
    }
}

// finalize BN3 + pooled
__global__ void k_fin3pool(const float* __restrict__ g, const float* __restrict__ be){
    int c = threadIdx.x;
    int b = blockIdx.x;
    float invM = 1.f/(float)MTOT;
    float s = g_sum3[c]*invM;
    float q = g_sq3[c]*invM;
    float v = fmaxf(q - s*s, 0.f);
    float sc = g[c]*rsqrtf(v+EPSBN);
    float sh = fmaf(-s, sc, be[c]);
    float mx = keyf(g_maxk[b*H1+c]);
    float mn = keyf(g_mink[b*H1+c]);
    float val = (sc >= 0.f) ? fmaf(mx, sc, sh) : fmaf(mn, sc, sh);
    g_pool[b*H1+c] = fmaxf(val, 0.f);
}

// e2 linear
__global__ __launch_bounds__(512) void k_e2(const float* __restrict__ W, const float* __restrict__ bias){
    __shared__ float sp[H1];
    int b = blockIdx.x, c = threadIdx.x;
    sp[c] = g_pool[b*H1 + c];
    __syncthreads();
    float acc = bias[c];
    #pragma unroll 4
    for (int f=0; f<H1; f++) acc = fmaf(sp[f], W[(size_t)f*H1 + c], acc);
    g_pre4[b*H1 + c] = acc;
}

// e2 BN(M=16)+ReLU -> code; decoder per-batch dots; analytic d1 BN params
__global__ __launch_bounds__(512) void k_code2(
    const float* __restrict__ eg, const float* __restrict__ ebe,
    const float* __restrict__ d1w, const float* __restrict__ d1b,
    const float* __restrict__ d1g, const float* __restrict__ d1be,
    const float* __restrict__ d2w, const float* __restrict__ d2b)
{
    __shared__ float scm[BB*H1];
    int t = threadIdx.x;
    float vals[16]; float s = 0.f;
    #pragma unroll
    for (int b=0;b<16;b++){ vals[b]=g_pre4[b*H1+t]; s+=vals[b]; }
    float m = s*(1.f/16.f);
    float q = 0.f;
    #pragma unroll
    for (int b=0;b<16;b++){ float d=vals[b]-m; q+=d*d; }
    float scl = eg[t]*rsqrtf(q*(1.f/16.f)+EPSBN);
    float sh = ebe[t];
    #pragma unroll
    for (int b=0;b<16;b++) scm[b*H1+t] = fmaxf(fmaf(vals[b]-m, scl, sh), 0.f);
    __syncthreads();

    int w = t>>5, lane = t&31;
    if (w < 6){
        for (int d = w*16; d < w*16+16; d++){
            int layer = d/48; int r = d%48; int b = r/3; int c = r%3;
            const float* Wd = layer ? d2w : d1w;
            float p = 0.f;
            for (int f=lane; f<H1; f+=32) p = fmaf(scm[b*H1+f], Wd[f*3+c], p);
            #pragma unroll
            for (int o=16;o;o>>=1) p += __shfl_xor_sync(0xffffffffu, p, o);
            if (lane==0){
                if (layer) g_dc2[b*3+c] = p + d2b[c];
                else       g_dc1[b*3+c] = p + d1b[c];
            }
        }
    }
    __syncthreads();
    if (w < 3){
        float wx = d1w[1536 + w], wy = d1w[1539 + w];
        float sG = 0.f;
        for (int n=lane; n<NN; n+=32){
            int ix = n/65, iy = n - ix*65;
            float gx = 1.f + ix*(119.f/128.f);
            float gy = 1.f + iy*(59.f/64.f);
            sG += gx*wx + gy*wy;
        }
        #pragma unroll
        for (int o=16;o;o>>=1) sG += __shfl_xor_sync(0xffffffffu, sG, o);
        float mG = sG*(1.f/8192.f);
        float qG = 0.f;
        for (int n=lane; n<NN; n+=32){
            int ix = n/65, iy = n - ix*65;
            float gx = 1.f + ix*(119.f/128.f);
            float gy = 1.f + iy*(59.f/64.f);
            float d = gx*wx + gy*wy - mG;
            qG += d*d;
        }
        #pragma unroll
        for (int o=16;o;o>>=1) qG += __shfl_xor_sync(0xffffffffu, qG, o);
        if (lane==0){
            float vG = qG*(1.f/8192.f);
            float sA=0.f;
            #pragma unroll
            for (int b=0;b<16;b++) sA += g_dc1[b*3+w];
            float mA = sA*(1.f/16.f);
            float qA=0.f;
            #pragma unroll
            for (int b=0;b<16;b++){ float d=g_dc1[b*3+w]-mA; qA+=d*d; }
            float vA = qA*(1.f/16.f);
            float mean = mA + mG;
            float var = fmaxf(vA + vG, 0.f);
            float sc1 = d1g[w]*rsqrtf(var+EPSBN);
            g_d1p[w]=sc1; g_d1p[3+w]= d1be[w] - mean*sc1;
        }
    }
}

// decode stats only (no z2 materialization)
__global__ __launch_bounds__(256) void k_decode(const float* __restrict__ d1w, const float* __restrict__ d2w){
    __shared__ float ss[3], sq_[3];
    int t = threadIdx.x;
    if (t<3){ ss[t]=0.f; sq_[t]=0.f; }
    __syncthreads();
    int gi = blockIdx.x*256 + t;
    int n = gi & (NN-1);
    int b = gi >> 13;
    int ix = n/65, iy = n - ix*65;
    float gx = 1.f + ix*(119.f/128.f);
    float gy = 1.f + iy*(59.f/64.f);
    float z1[3];
    #pragma unroll
    for (int c=0;c<3;c++){
        float pre = g_dc1[b*3+c] + gx*d1w[1536+c] + gy*d1w[1539+c];
        z1[c] = fmaxf(fmaf(pre, g_d1p[c], g_d1p[3+c]), 0.f);
    }
    int lane = t & 31;
    #pragma unroll
    for (int c=0;c<3;c++){
        float v = g_dc2[b*3+c] + z1[0]*d2w[1536+c] + z1[1]*d2w[1539+c] + z1[2]*d2w[1542+c];
        float sv = v, qv = v*v;
        #pragma unroll
        for (int o=16;o;o>>=1){ sv += __shfl_xor_sync(0xffffffffu, sv, o); qv += __shfl_xor_sync(0xffffffffu, qv, o); }
        if (lane==0){ atomicAdd(&ss[c], sv); atomicAdd(&sq_[c], qv); }
    }
    __syncthreads();
    if (t<3){ atomicAdd(&g_sumd[t], ss[t]); atomicAdd(&g_sqd[t], sq_[t]); }
}

// out: recompute decoder output analytically + final BN+ReLU
__global__ __launch_bounds__(256) void k_out(
    float* __restrict__ out, const float* __restrict__ d1w, const float* __restrict__ d2w,
    const float* __restrict__ g, const float* __restrict__ be)
{
    int gi = blockIdx.x*256 + threadIdx.x;
    int n = gi & (NN-1);
    int b = gi >> 13;
    int ix = n/65, iy = n - ix*65;
    float gx = 1.f + ix*(119.f/128.f);
    float gy = 1.f + iy*(59.f/64.f);
    float z1[3];
    #pragma unroll
    for (int c=0;c<3;c++){
        float pre = g_dc1[b*3+c] + gx*d1w[1536+c] + gy*d1w[1539+c];
        z1[c] = fmaxf(fmaf(pre, g_d1p[c], g_d1p[3+c]), 0.f);
    }
    float invM = 1.f/(float)MTOT;
    #pragma unroll
    for (int c=0;c<3;c++){
        float v = g_dc2[b*3+c] + z1[0]*d2w[1536+c] + z1[1]*d2w[1539+c] + z1[2]*d2w[1542+c];
        float m = g_sumd[c]*invM;
        float var = fmaxf(g_sqd[c]*invM - m*m, 0.f);
        float sc = g[c]*rsqrtf(var+EPSBN);
        out[(size_t)gi*3 + c] = fmaxf(fmaf(v-m, sc, be[c]), 0.f);
    }
}

// ---------------- launch ----------------
extern "C" void kernel_launch(void* const* d_in, const int* in_sizes, int n_in,
                              void* d_out, int out_size)
{
    const float* data = (const float*)d_in[0];
    const int*   knn  = (const int*)  d_in[1];
    const float* e1w  = (const float*)d_in[2];
    const float* e1b  = (const float*)d_in[3];
    const float* e1g  = (const float*)d_in[4];
    const float* e1be = (const float*)d_in[5];
    const float* gc1w = (const float*)d_in[6];
    const float* g1g  = (const float*)d_in[8];
    const float* g1be = (const float*)d_in[9];
    const float* gc2w = (const float*)d_in[10];
    const float* g2g  = (const float*)d_in[12];
    const float* g2be = (const float*)d_in[13];
    const float* e2w  = (const float*)d_in[14];
    const float* e2b  = (const float*)d_in[15];
    const float* e2g  = (const float*)d_in[16];
    const float* e2be = (const float*)d_in[17];
    const float* d1w  = (const float*)d_in[18];
    const float* d1b  = (const float*)d_in[19];
    const float* d1g  = (const float*)d_in[20];
    const float* d1be = (const float*)d_in[21];
    const float* d2w  = (const float*)d_in[22];
    const float* d2b  = (const float*)d_in[23];
    const float* d2g  = (const float*)d_in[24];
    const float* d2be = (const float*)d_in[25];
    float* out = (float*)d_out;

    cudaFuncSetAttribute(k_gemm1f, cudaFuncAttributeMaxDynamicSharedMemorySize, G1_SMEM);
    cudaFuncSetAttribute(k_gemm2f, cudaFuncAttributeMaxDynamicSharedMemorySize, G2_SMEM);

    k_init<<<256, 256>>>(gc1w, gc2w);
    k_cov_e1<<<MTOT/256, 256>>>(data, knn, e1w, e1b);
    k_gemm1f<<<MTOT/128, 256, G1_SMEM>>>(knn, e1g, e1be);
    k_gemm2f<<<MTOT/128, 512, G2_SMEM>>>(knn, g1g, g1be);
    k_fin3pool<<<BB, H1>>>(g2g, g2be);
    k_e2<<<BB, H1>>>(e2w, e2b);
    k_code2<<<1, 512>>>(e2g, e2be, d1w, d1b, d1g, d1be, d2w, d2b);
    k_decode<<<MTOT/256, 256>>>(d1w, d2w);
    k_out<<<MTOT/256, 256>>>(out, d1w, d2w, d2g, d2be);
}

// round 9
// speedup vs baseline: 1.0789x; 1.0789x over previous
#include <cuda_runtime.h>
#include <cuda_bf16.h>
#include <cstdint>

#define BB   16
#define NN   8192
#define KNB  16
#define MTOT (BB*NN)      // 131072
#define H3   64
#define H2   128
#define H1   512
#define EPSBN 1e-5f

typedef unsigned long long ull;
typedef unsigned int uint;

// ---------------- scratch ----------------
__device__ float g_pre1[MTOT*H3];
__device__ uint  g_a1hi[MTOT*32];
__device__ uint  g_a1lo[MTOT*32];
__device__ float g_pre2[MTOT*H2];
__device__ uint  g_a2hi[MTOT*64];
__device__ uint  g_a2lo[MTOT*64];
__device__ unsigned short g_w1hi[H2*H3];
__device__ unsigned short g_w1lo[H2*H3];
__device__ unsigned short g_w2hi[H1*H2];
__device__ unsigned short g_w2lo[H1*H2];
__device__ float g_sum1[H3], g_sq1[H3];
__device__ float g_sum2[H2], g_sq2[H2];
__device__ float g_sum3[H1], g_sq3[H1];
__device__ uint  g_maxk[BB*H1], g_mink[BB*H1];
__device__ float g_pool[BB*H1];
__device__ float g_pre4[BB*H1];
__device__ float g_dc1[BB*3], g_dc2[BB*3];
__device__ float g_d1p[6];
__device__ float g_sumd[3], g_sqd[3];

// ---------------- helpers ----------------
__device__ __forceinline__ uint fkey(float f){
    uint u = __float_as_uint(f);
    return (u & 0x80000000u) ? ~u : (u | 0x80000000u);
}
__device__ __forceinline__ float keyf(uint k){
    uint u = (k & 0x80000000u) ? (k ^ 0x80000000u) : ~k;
    return __uint_as_float(u);
}
__device__ __forceinline__ uint smem_u32(const void* p){
    uint a; asm("{ .reg .u64 t; cvta.to.shared.u64 t, %1; cvt.u32.u64 %0, t; }" : "=r"(a) : "l"(p)); return a;
}
__device__ __forceinline__ uint pbf2(float a, float b){
    __nv_bfloat162 h = __floats2bfloat162_rn(a, b);
    return *(uint*)&h;
}
__device__ __forceinline__ void ldm4(uint* r, uint addr){
    asm volatile("ldmatrix.sync.aligned.m8n8.x4.shared.b16 {%0,%1,%2,%3}, [%4];"
        : "=r"(r[0]),"=r"(r[1]),"=r"(r[2]),"=r"(r[3]) : "r"(addr));
}
__device__ __forceinline__ void mma16816(float* d, const uint* a, uint b0, uint b1){
    asm volatile("mma.sync.aligned.m16n8k16.row.col.f32.bf16.bf16.f32 "
        "{%0,%1,%2,%3}, {%4,%5,%6,%7}, {%8,%9}, {%0,%1,%2,%3};"
        : "+f"(d[0]),"+f"(d[1]),"+f"(d[2]),"+f"(d[3])
        : "r"(a[0]),"r"(a[1]),"r"(a[2]),"r"(a[3]), "r"(b0),"r"(b1));
}

// ---------------- init: zero stats + split both weight matrices ----------------
__global__ void k_init(const float* __restrict__ w1, const float* __restrict__ w2){
    int i = blockIdx.x*blockDim.x + threadIdx.x;
    if (i < H1*H2){
        int c = i >> 7, k = i & 127;
        float v = w2[(size_t)k*H1 + c];
        __nv_bfloat16 h = __float2bfloat16_rn(v);
        float r = v - __bfloat162float(h);
        __nv_bfloat16 l = __float2bfloat16_rn(r);
        g_w2hi[i] = *(unsigned short*)&h;
        g_w2lo[i] = *(unsigned short*)&l;
    }
    if (i < H2*H3){
        int c = i >> 6, k = i & 63;
        float v = w1[(size_t)k*H2 + c];
        __nv_bfloat16 h = __float2bfloat16_rn(v);
        float r = v - __bfloat162float(h);
        __nv_bfloat16 l = __float2bfloat16_rn(r);
        g_w1hi[i] = *(unsigned short*)&h;
        g_w1lo[i] = *(unsigned short*)&l;
    }
    if (i < BB*H1){ g_maxk[i]=0u; g_mink[i]=0xFFFFFFFFu; }
    if (i < H1){ g_sum3[i]=0.f; g_sq3[i]=0.f; }
    if (i < H2){ g_sum2[i]=0.f; g_sq2[i]=0.f; }
    if (i < H3){ g_sum1[i]=0.f; g_sq1[i]=0.f; }
    if (i < 3){ g_sumd[i]=0.f; g_sqd[i]=0.f; }
}

// covariance features + Linear(12,64) + BN stats
__global__ __launch_bounds__(256) void k_cov_e1(
    const float* __restrict__ data, const int* __restrict__ knn,
    const float* __restrict__ w, const float* __restrict__ bias)
{
    __shared__ float Ws[12*H3];
    __shared__ float bs[H3];
    __shared__ float x0s[256*12];
    __shared__ float ssum[H3], ssq[H3];
    int t = threadIdx.x;
    for (int i = t; i < 12*H3; i += 256) Ws[i] = w[i];
    if (t < H3){ bs[t] = bias[t]; ssum[t]=0.f; ssq[t]=0.f; }

    int gi = blockIdx.x*256 + t;
    int b = gi >> 13;
    const int* kp = knn + (size_t)gi*KNB;
    float sx=0,sy=0,sz=0,sxx=0,sxy=0,sxz=0,syy=0,syz=0,szz=0;
    #pragma unroll
    for (int k=0;k<KNB;k++){
        int j = kp[k];
        const float* p = data + ((size_t)(b*NN + j))*3;
        float x=p[0], y=p[1], z=p[2];
        sx+=x; sy+=y; sz+=z;
        sxx+=x*x; sxy+=x*y; sxz+=x*z; syy+=y*y; syz+=y*z; szz+=z*z;
    }
    float mx=sx*(1.f/16.f), my=sy*(1.f/16.f), mz=sz*(1.f/16.f);
    const float i15 = 1.f/15.f;
    float cxx=(sxx-16.f*mx*mx)*i15, cxy=(sxy-16.f*mx*my)*i15, cxz=(sxz-16.f*mx*mz)*i15;
    float cyy=(syy-16.f*my*my)*i15, cyz=(syz-16.f*my*mz)*i15, czz=(szz-16.f*mz*mz)*i15;
    float* xr = &x0s[t*12];
    xr[0]=data[(size_t)gi*3+0]; xr[1]=data[(size_t)gi*3+1]; xr[2]=data[(size_t)gi*3+2];
    xr[3]=cxx; xr[4]=cxy; xr[5]=cxz; xr[6]=cxy; xr[7]=cyy; xr[8]=cyz; xr[9]=cxz; xr[10]=cyz; xr[11]=czz;
    __syncthreads();

    int c = t & 63;
    float bsum=0.f, bsq=0.f;
    float* outp = g_pre1 + (size_t)blockIdx.x*256*H3;
    #pragma unroll 4
    for (int kq=0;kq<64;kq++){
        int e = t + kq*256;
        const float* x0 = &x0s[(e>>6)*12];
        float v = bs[c];
        #pragma unroll
        for (int j=0;j<12;j++) v = fmaf(x0[j], Ws[j*H3+c], v);
        outp[e] = v;
        bsum += v; bsq += v*v;
    }
    atomicAdd(&ssum[c], bsum); atomicAdd(&ssq[c], bsq);
    __syncthreads();
    if (t < H3){ atomicAdd(&g_sum1[t], ssum[t]); atomicAdd(&g_sq1[t], ssq[t]); }
}

// layer1 agg: inline BN + ReLU gather, /17 -> bf16 hi/lo
__global__ __launch_bounds__(256) void k_agg1(const int* __restrict__ knn,
    const float* __restrict__ eg, const float* __restrict__ ebe){
    const int TPN = H3/4;         // 16
    const int NPB = 256/TPN;      // 16
    __shared__ int sidx[NPB][KNB];
    int t = threadIdx.x;
    int n0 = blockIdx.x*NPB;
    if (t < NPB*KNB) sidx[t>>4][t&15] = knn[(size_t)(n0 + (t>>4))*KNB + (t&15)];
    __syncthreads();
    int nl = t / TPN; int c4 = t % TPN;
    int gi = n0 + nl;
    int base = (gi >> 13) * NN;
    const float4* pre = (const float4*)g_pre1;
    // inline BN params for my 4 channels
    float4 sc, sh;
    {
        const float invM = 1.f/(float)MTOT;
        float m, v, s;
        int c = c4*4;
        m = g_sum1[c]*invM;   v = fmaxf(g_sq1[c]*invM - m*m, 0.f);   s = eg[c]*rsqrtf(v+EPSBN);   sc.x=s; sh.x=fmaf(-m,s,ebe[c]);
        m = g_sum1[c+1]*invM; v = fmaxf(g_sq1[c+1]*invM - m*m, 0.f); s = eg[c+1]*rsqrtf(v+EPSBN); sc.y=s; sh.y=fmaf(-m,s,ebe[c+1]);
        m = g_sum1[c+2]*invM; v = fmaxf(g_sq1[c+2]*invM - m*m, 0.f); s = eg[c+2]*rsqrtf(v+EPSBN); sc.z=s; sh.z=fmaf(-m,s,ebe[c+2]);
        m = g_sum1[c+3]*invM; v = fmaxf(g_sq1[c+3]*invM - m*m, 0.f); s = eg[c+3]*rsqrtf(v+EPSBN); sc.w=s; sh.w=fmaf(-m,s,ebe[c+3]);
    }
    float4 p = pre[(size_t)gi*TPN + c4];
    float ax = fmaxf(fmaf(p.x, sc.x, sh.x), 0.f);
    float ay = fmaxf(fmaf(p.y, sc.y, sh.y), 0.f);
    float az = fmaxf(fmaf(p.z, sc.z, sh.z), 0.f);
    float aw = fmaxf(fmaf(p.w, sc.w, sh.w), 0.f);
    #pragma unroll
    for (int k=0;k<KNB;k++){
        int nb = base + sidx[nl][k];
        float4 q = pre[(size_t)nb*TPN + c4];
        ax += fmaxf(fmaf(q.x, sc.x, sh.x), 0.f);
        ay += fmaxf(fmaf(q.y, sc.y, sh.y), 0.f);
        az += fmaxf(fmaf(q.z, sc.z, sh.z), 0.f);
        aw += fmaxf(fmaf(q.w, sc.w, sh.w), 0.f);
    }
    const float s = 1.f/17.f;
    ax*=s; ay*=s; az*=s; aw*=s;
    __nv_bfloat162 h01 = __floats2bfloat162_rn(ax, ay);
    __nv_bfloat162 h23 = __floats2bfloat162_rn(az, aw);
    size_t o = (size_t)gi*32 + c4*2;
    g_a1hi[o]   = *(uint*)&h01;
    g_a1hi[o+1] = *(uint*)&h23;
    g_a1lo[o]   = pbf2(ax - __bfloat162float(h01.x), ay - __bfloat162float(h01.y));
    g_a1lo[o+1] = pbf2(az - __bfloat162float(h23.x), aw - __bfloat162float(h23.y));
}

// layer2 agg: inline BN + ReLU gather, /17 -> bf16 hi/lo
__global__ __launch_bounds__(256) void k_agg2(const int* __restrict__ knn,
    const float* __restrict__ gg, const float* __restrict__ gbe){
    const int TPN = H2/4;         // 32
    const int NPB = 256/TPN;      // 8
    __shared__ int sidx[NPB][KNB];
    int t = threadIdx.x;
    int n0 = blockIdx.x*NPB;
    if (t < NPB*KNB) sidx[t>>4][t&15] = knn[(size_t)(n0 + (t>>4))*KNB + (t&15)];
    __syncthreads();
    int nl = t / TPN; int c4 = t % TPN;
    int gi = n0 + nl;
    int base = (gi >> 13) * NN;
    const float4* pre = (const float4*)g_pre2;
    float4 sc, sh;
    {
        const float invM = 1.f/(float)MTOT;
        float m, v, s;
        int c = c4*4;
        m = g_sum2[c]*invM;   v = fmaxf(g_sq2[c]*invM - m*m, 0.f);   s = gg[c]*rsqrtf(v+EPSBN);   sc.x=s; sh.x=fmaf(-m,s,gbe[c]);
        m = g_sum2[c+1]*invM; v = fmaxf(g_sq2[c+1]*invM - m*m, 0.f); s = gg[c+1]*rsqrtf(v+EPSBN); sc.y=s; sh.y=fmaf(-m,s,gbe[c+1]);
        m = g_sum2[c+2]*invM; v = fmaxf(g_sq2[c+2]*invM - m*m, 0.f); s = gg[c+2]*rsqrtf(v+EPSBN); sc.z=s; sh.z=fmaf(-m,s,gbe[c+2]);
        m = g_sum2[c+3]*invM; v = fmaxf(g_sq2[c+3]*invM - m*m, 0.f); s = gg[c+3]*rsqrtf(v+EPSBN); sc.w=s; sh.w=fmaf(-m,s,gbe[c+3]);
    }
    float4 p = pre[(size_t)gi*TPN + c4];
    float ax = fmaxf(fmaf(p.x, sc.x, sh.x), 0.f);
    float ay = fmaxf(fmaf(p.y, sc.y, sh.y), 0.f);
    float az = fmaxf(fmaf(p.z, sc.z, sh.z), 0.f);
    float aw = fmaxf(fmaf(p.w, sc.w, sh.w), 0.f);
    #pragma unroll
    for (int k=0;k<KNB;k++){
        int nb = base + sidx[nl][k];
        float4 q = pre[(size_t)nb*TPN + c4];
        ax += fmaxf(fmaf(q.x, sc.x, sh.x), 0.f);
        ay += fmaxf(fmaf(q.y, sc.y, sh.y), 0.f);
        az += fmaxf(fmaf(q.z, sc.z, sh.z), 0.f);
        aw += fmaxf(fmaf(q.w, sc.w, sh.w), 0.f);
    }
    const float s = 1.f/17.f;
    ax*=s; ay*=s; az*=s; aw*=s;
    __nv_bfloat162 h01 = __floats2bfloat162_rn(ax, ay);
    __nv_bfloat162 h23 = __floats2bfloat162_rn(az, aw);
    size_t o = (size_t)gi*64 + c4*2;
    g_a2hi[o]   = *(uint*)&h01;
    g_a2hi[o+1] = *(uint*)&h23;
    g_a2lo[o]   = pbf2(ax - __bfloat162float(h01.x), ay - __bfloat162float(h01.y));
    g_a2lo[o+1] = pbf2(az - __bfloat162float(h23.x), aw - __bfloat162float(h23.y));
}

// ---------------- gemm1: mma bf16 split (128 nodes x 128 cols, K=64) ----------------
#define AH1_OFF 0u
#define AL1_OFF 18432u
#define BH1_OFF 36864u
#define BL1_OFF 55296u
#define S1SUM_OFF 73728u
#define S1SQ_OFF  74240u
#define G1_SMEM   74752

__global__ void __launch_bounds__(256, 2) k_gemm1_mma(){
    extern __shared__ __align__(16) char sm[];
    uint sb = smem_u32(sm);
    int t = threadIdx.x, lane = t & 31, wid = t >> 5;
    int wm = wid >> 2, wn = wid & 3;
    int node0 = blockIdx.x*128;

    float* ssum = (float*)(sm + S1SUM_OFF);
    float* ssq  = (float*)(sm + S1SQ_OFF);

    {
        int row = t >> 1, half = t & 1;
        const uint4* ph = (const uint4*)(g_a1hi + (size_t)(node0+row)*32) + half*4;
        const uint4* pl = (const uint4*)(g_a1lo + (size_t)(node0+row)*32) + half*4;
        uint4* dh = (uint4*)(sm + AH1_OFF + row*144 + half*64);
        uint4* dl = (uint4*)(sm + AL1_OFF + row*144 + half*64);
        #pragma unroll
        for (int i=0;i<4;i++){ dh[i] = ph[i]; dl[i] = pl[i]; }
    }
    {
        int col = t >> 1, half = t & 1;
        const uint4* ph = (const uint4*)((const char*)g_w1hi + (size_t)col*128) + half*4;
        const uint4* pl = (const uint4*)((const char*)g_w1lo + (size_t)col*128) + half*4;
        uint4* dh = (uint4*)(sm + BH1_OFF + col*144 + half*64);
        uint4* dl = (uint4*)(sm + BL1_OFF + col*144 + half*64);
        #pragma unroll
        for (int i=0;i<4;i++){ dh[i] = ph[i]; dl[i] = pl[i]; }
    }
    if (t < 128){ ssum[t]=0.f; ssq[t]=0.f; }
    __syncthreads();

    uint aBase = sb + AH1_OFF + (uint)((wm*64 + (lane & 15))*144 + (lane >> 4)*16);
    uint bBase = sb + BH1_OFF + (uint)((wn*32 + (lane & 7) + ((lane >> 4) & 1)*8)*144 + ((lane >> 3) & 1)*16);

    float acc[4][4][4];
    #pragma unroll
    for (int mi=0;mi<4;mi++)
        #pragma unroll
        for (int j=0;j<4;j++)
            #pragma unroll
            for (int r=0;r<4;r++) acc[mi][j][r] = 0.f;

    #pragma unroll
    for (int ks=0; ks<4; ks++){
        uint bh[8], bl[8];
        ldm4(bh,   bBase + ks*32);
        ldm4(bh+4, bBase + 16*144 + ks*32);
        ldm4(bl,   bBase + (BL1_OFF-BH1_OFF) + ks*32);
        ldm4(bl+4, bBase + (BL1_OFF-BH1_OFF) + 16*144 + ks*32);
        #pragma unroll
        for (int mi=0; mi<4; mi++){
            uint ah[4], al[4];
            ldm4(ah, aBase + mi*16*144 + ks*32);
            ldm4(al, aBase + (AL1_OFF-AH1_OFF) + mi*16*144 + ks*32);
            #pragma unroll
            for (int j=0;j<4;j++){
                mma16816(acc[mi][j], ah, bh[2*j], bh[2*j+1]);
                mma16816(acc[mi][j], al, bh[2*j], bh[2*j+1]);
                mma16816(acc[mi][j], ah, bl[2*j], bl[2*j+1]);
            }
        }
    }

    #pragma unroll
    for (int mi=0;mi<4;mi++){
        int r0 = node0 + wm*64 + mi*16 + (lane >> 2);
        #pragma unroll
        for (int j=0;j<4;j++){
            int c0 = wn*32 + j*8 + (lane & 3)*2;
            *(float2*)&g_pre2[(size_t)r0*H2 + c0]     = make_float2(acc[mi][j][0], acc[mi][j][1]);
            *(float2*)&g_pre2[(size_t)(r0+8)*H2 + c0] = make_float2(acc[mi][j][2], acc[mi][j][3]);
        }
    }
    #pragma unroll
    for (int j=0;j<4;j++){
        #pragma unroll
        for (int p=0;p<2;p++){
            float s=0.f, qq=0.f;
            #pragma unroll
            for (int mi=0;mi<4;mi++){
                #pragma unroll
                for (int r=0;r<2;r++){
                    float v = acc[mi][j][2*r+p];
                    s += v; qq = fmaf(v, v, qq);
                }
            }
            #pragma unroll
            for (int o=4;o<32;o<<=1){
                s  += __shfl_xor_sync(0xffffffffu, s, o);
                qq += __shfl_xor_sync(0xffffffffu, qq, o);
            }
            if (lane < 4){
                int colq = wn*32 + j*8 + lane*2 + p;
                atomicAdd(&ssum[colq], s);
                atomicAdd(&ssq[colq], qq);
            }
        }
    }
    __syncthreads();
    if (t < 128){
        atomicAdd(&g_sum2[t], ssum[t]);
        atomicAdd(&g_sq2[t], ssq[t]);
    }
}

// ---------------- gemm2: mma bf16 split, two B-passes (hi, lo) for 2 CTAs/SM ----------------
#define AH_OFF 0u
#define AL_OFF 34816u
#define B_OFF  69632u
#define SSUM_OFF 104448u
#define SSQ_OFF  104960u
#define SMX_OFF  105472u
#define SMN_OFF  105984u
#define G2_SMEM  106496

__global__ void __launch_bounds__(256, 2) k_gemm2_mma(){
    extern __shared__ __align__(16) char sm[];
    uint sb = smem_u32(sm);
    int t = threadIdx.x, lane = t & 31, wid = t >> 5;
    int wm = wid >> 2, wn = wid & 3;
    int node0 = blockIdx.x*128;
    int batch = blockIdx.x >> 6;

    float* ssum = (float*)(sm + SSUM_OFF);
    float* ssq  = (float*)(sm + SSQ_OFF);
    uint*  smx  = (uint*)(sm + SMX_OFF);
    uint*  smn  = (uint*)(sm + SMN_OFF);

    // load A hi/lo (128 rows x 256B, stride 272B)
    {
        int row = t >> 1, half = t & 1;
        const uint4* ph = (const uint4*)(g_a2hi + (size_t)(node0+row)*64) + half*8;
        const uint4* pl = (const uint4*)(g_a2lo + (size_t)(node0+row)*64) + half*8;
        uint4* dh = (uint4*)(sm + AH_OFF + row*272 + half*128);
        uint4* dl = (uint4*)(sm + AL_OFF + row*272 + half*128);
        #pragma unroll
        for (int i=0;i<8;i++){ dh[i] = ph[i]; dl[i] = pl[i]; }
    }

    uint aBase = sb + AH_OFF + (uint)((wm*64 + (lane & 15))*272 + (lane >> 4)*16);
    uint bBase = sb + B_OFF  + (uint)((wn*32 + (lane & 7) + ((lane >> 4) & 1)*8)*272 + ((lane >> 3) & 1)*16);

    for (int q = 0; q < 4; q++){
        int cb = q*128;
        if (t < 128){ ssum[t]=0.f; ssq[t]=0.f; smx[t]=0u; smn[t]=0xFFFFFFFFu; }

        float acc[4][4][4];
        #pragma unroll
        for (int mi=0;mi<4;mi++)
            #pragma unroll
            for (int j=0;j<4;j++)
                #pragma unroll
                for (int r=0;r<4;r++) acc[mi][j][r] = 0.f;

        #pragma unroll
        for (int pass=0; pass<2; pass++){
            // load B pass (hi or lo): 128 cols x 256B, stride 272
            {
                const char* src = pass ? (const char*)g_w2lo : (const char*)g_w2hi;
                int col = t >> 1, half = t & 1;
                const uint4* pb = (const uint4*)(src + (size_t)(cb+col)*256) + half*8;
                uint4* db = (uint4*)(sm + B_OFF + col*272 + half*128);
                #pragma unroll
                for (int i=0;i<8;i++) db[i] = pb[i];
            }
            __syncthreads();

            #pragma unroll
            for (int ks=0; ks<8; ks++){
                uint bq[8];
                ldm4(bq,   bBase + ks*32);
                ldm4(bq+4, bBase + 16*272 + ks*32);
                #pragma unroll
                for (int mi=0; mi<4; mi++){
                    uint ah[4];
                    ldm4(ah, aBase + mi*16*272 + ks*32);
                    if (pass == 0){
                        uint al[4];
                        ldm4(al, aBase + (AL_OFF-AH_OFF) + mi*16*272 + ks*32);
                        #pragma unroll
                        for (int j=0;j<4;j++){
                            mma16816(acc[mi][j], ah, bq[2*j], bq[2*j+1]);
                            mma16816(acc[mi][j], al, bq[2*j], bq[2*j+1]);
                        }
                    } else {
                        #pragma unroll
                        for (int j=0;j<4;j++)
                            mma16816(acc[mi][j], ah, bq[2*j], bq[2*j+1]);
                    }
                }
            }
            __syncthreads();
        }

        // per-column stats
        #pragma unroll
        for (int j=0;j<4;j++){
            #pragma unroll
            for (int p=0;p<2;p++){
                float s=0.f, qq=0.f, mx=-3.402823466e38f, mn=3.402823466e38f;
                #pragma unroll
                for (int mi=0;mi<4;mi++){
                    #pragma unroll
                    for (int r=0;r<2;r++){
                        float v = acc[mi][j][2*r+p];
                        s += v; qq = fmaf(v, v, qq);
                        mx = fmaxf(mx, v); mn = fminf(mn, v);
                    }
                }
                #pragma unroll
                for (int o=4;o<32;o<<=1){
                    s  += __shfl_xor_sync(0xffffffffu, s, o);
                    qq += __shfl_xor_sync(0xffffffffu, qq, o);
                    mx = fmaxf(mx, __shfl_xor_sync(0xffffffffu, mx, o));
                    mn = fminf(mn, __shfl_xor_sync(0xffffffffu, mn, o));
                }
                if (lane < 4){
                    int colq = wn*32 + j*8 + lane*2 + p;
                    atomicAdd(&ssum[colq], s);
                    atomicAdd(&ssq[colq], qq);
                    atomicMax(&smx[colq], fkey(mx));
                    atomicMin(&smn[colq], fkey(mn));
                }
            }
        }
        __syncthreads();
        if (t < 128){
            atomicAdd(&g_sum3[cb+t], ssum[t]);
            atomicAdd(&g_sq3[cb+t], ssq[t]);
            atomicMax(&g_maxk[batch*H1 + cb + t], smx[t]);
            atomicMin(&g_mink[batch*H1 + cb + t], smn[t]);
        }
        __syncthreads();
    }
}

// finalize BN3 + pooled
__global__ void k_fin3pool(const float* __restrict__ g, const float* __restrict__ be){
    int c = threadIdx.x;
    int b = blockIdx.x;
    float invM = 1.f/(float)MTOT;
    float s = g_sum3[c]*invM;
    float q = g_sq3[c]*invM;
    float v = fmaxf(q - s*s, 0.f);
    float sc = g[c]*rsqrtf(v+EPSBN);
    float sh = fmaf(-s, sc, be[c]);
    float mx = keyf(g_maxk[b*H1+c]);
    float mn = keyf(g_mink[b*H1+c]);
    float val = (sc >= 0.f) ? fmaf(mx, sc, sh) : fmaf(mn, sc, sh);
    g_pool[b*H1+c] = fmaxf(val, 0.f);
}

// e2 linear
__global__ __launch_bounds__(512) void k_e2(const float* __restrict__ W, const float* __restrict__ bias){
    __shared__ float sp[H1];
    int b = blockIdx.x, c = threadIdx.x;
    sp[c] = g_pool[b*H1 + c];
    __syncthreads();
    float acc = bias[c];
    #pragma unroll 4
    for (int f=0; f<H1; f++) acc = fmaf(sp[f], W[(size_t)f*H1 + c], acc);
    g_pre4[b*H1 + c] = acc;
}

// e2 BN(M=16)+ReLU -> code; decoder per-batch dots; analytic d1 BN params
__global__ __launch_bounds__(512) void k_code2(
    const float* __restrict__ eg, const float* __restrict__ ebe,
    const float* __restrict__ d1w, const float* __restrict__ d1b,
    const float* __restrict__ d1g, const float* __restrict__ d1be,
    const float* __restrict__ d2w, const float* __restrict__ d2b)
{
    __shared__ float scm[BB*H1];
    int t = threadIdx.x;
    float vals[16]; float s = 0.f;
    #pragma unroll
    for (int b=0;b<16;b++){ vals[b]=g_pre4[b*H1+t]; s+=vals[b]; }
    float m = s*(1.f/16.f);
    float q = 0.f;
    #pragma unroll
    for (int b=0;b<16;b++){ float d=vals[b]-m; q+=d*d; }
    float scl = eg[t]*rsqrtf(q*(1.f/16.f)+EPSBN);
    float sh = ebe[t];
    #pragma unroll
    for (int b=0;b<16;b++) scm[b*H1+t] = fmaxf(fmaf(vals[b]-m, scl, sh), 0.f);
    __syncthreads();

    int w = t>>5, lane = t&31;
    if (w < 6){
        for (int d = w*16; d < w*16+16; d++){
            int layer = d/48; int r = d%48; int b = r/3; int c = r%3;
            const float* Wd = layer ? d2w : d1w;
            float p = 0.f;
            for (int f=lane; f<H1; f+=32) p = fmaf(scm[b*H1+f], Wd[f*3+c], p);
            #pragma unroll
            for (int o=16;o;o>>=1) p += __shfl_xor_sync(0xffffffffu, p, o);
            if (lane==0){
                if (layer) g_dc2[b*3+c] = p + d2b[c];
                else       g_dc1[b*3+c] = p + d1b[c];
            }
        }
    }
    __syncthreads();
    if (w < 3){
        float wx = d1w[1536 + w], wy = d1w[1539 + w];
        float sG = 0.f;
        for (int n=lane; n<NN; n+=32){
            int ix = n/65, iy = n - ix*65;
            float gx = 1.f + ix*(119.f/128.f);
            float gy = 1.f + iy*(59.f/64.f);
            sG += gx*wx + gy*wy;
        }
        #pragma unroll
        for (int o=16;o;o>>=1) sG += __shfl_xor_sync(0xffffffffu, sG, o);
        float mG = sG*(1.f/8192.f);
        float qG = 0.f;
        for (int n=lane; n<NN; n+=32){
            int ix = n/65, iy = n - ix*65;
            float gx = 1.f + ix*(119.f/128.f);
            float gy = 1.f + iy*(59.f/64.f);
            float d = gx*wx + gy*wy - mG;
            qG += d*d;
        }
        #pragma unroll
        for (int o=16;o;o>>=1) qG += __shfl_xor_sync(0xffffffffu, qG, o);
        if (lane==0){
            float vG = qG*(1.f/8192.f);
            float sA=0.f;
            #pragma unroll
            for (int b=0;b<16;b++) sA += g_dc1[b*3+w];
            float mA = sA*(1.f/16.f);
            float qA=0.f;
            #pragma unroll
            for (int b=0;b<16;b++){ float d=g_dc1[b*3+w]-mA; qA+=d*d; }
            float vA = qA*(1.f/16.f);
            float mean = mA + mG;
            float var = fmaxf(vA + vG, 0.f);
            float sc1 = d1g[w]*rsqrtf(var+EPSBN);
            g_d1p[w]=sc1; g_d1p[3+w]= d1be[w] - mean*sc1;
        }
    }
}

// decode stats only
__global__ __launch_bounds__(256) void k_decode(const float* __restrict__ d1w, const float* __restrict__ d2w){
    __shared__ float ss[3], sq_[3];
    int t = threadIdx.x;
    if (t<3){ ss[t]=0.f; sq_[t]=0.f; }
    __syncthreads();
    int gi = blockIdx.x*256 + t;
    int n = gi & (NN-1);
    int b = gi >> 13;
    int ix = n/65, iy = n - ix*65;
    float gx = 1.f + ix*(119.f/128.f);
    float gy = 1.f + iy*(59.f/64.f);
    float z1[3];
    #pragma unroll
    for (int c=0;c<3;c++){
        float pre = g_dc1[b*3+c] + gx*d1w[1536+c] + gy*d1w[1539+c];
        z1[c] = fmaxf(fmaf(pre, g_d1p[c], g_d1p[3+c]), 0.f);
    }
    int lane = t & 31;
    #pragma unroll
    for (int c=0;c<3;c++){
        float v = g_dc2[b*3+c] + z1[0]*d2w[1536+c] + z1[1]*d2w[1539+c] + z1[2]*d2w[1542+c];
        float sv = v, qv = v*v;
        #pragma unroll
        for (int o=16;o;o>>=1){ sv += __shfl_xor_sync(0xffffffffu, sv, o); qv += __shfl_xor_sync(0xffffffffu, qv, o); }
        if (lane==0){ atomicAdd(&ss[c], sv); atomicAdd(&sq_[c], qv); }
    }
    __syncthreads();
    if (t<3){ atomicAdd(&g_sumd[t], ss[t]); atomicAdd(&g_sqd[t], sq_[t]); }
}

// out: recompute decoder output analytically + final BN+ReLU
__global__ __launch_bounds__(256) void k_out(
    float* __restrict__ out, const float* __restrict__ d1w, const float* __restrict__ d2w,
    const float* __restrict__ g, const float* __restrict__ be)
{
    int gi = blockIdx.x*256 + threadIdx.x;
    int n = gi & (NN-1);
    int b = gi >> 13;
    int ix = n/65, iy = n - ix*65;
    float gx = 1.f + ix*(119.f/128.f);
    float gy = 1.f + iy*(59.f/64.f);
    float z1[3];
    #pragma unroll
    for (int c=0;c<3;c++){
        float pre = g_dc1[b*3+c] + gx*d1w[1536+c] + gy*d1w[1539+c];
        z1[c] = fmaxf(fmaf(pre, g_d1p[c], g_d1p[3+c]), 0.f);
    }
    float invM = 1.f/(float)MTOT;
    #pragma unroll
    for (int c=0;c<3;c++){
        float v = g_dc2[b*3+c] + z1[0]*d2w[1536+c] + z1[1]*d2w[1539+c] + z1[2]*d2w[1542+c];
        float m = g_sumd[c]*invM;
        float var = fmaxf(g_sqd[c]*invM - m*m, 0.f);
        float sc = g[c]*rsqrtf(var+EPSBN);
        out[(size_t)gi*3 + c] = fmaxf(fmaf(v-m, sc, be[c]), 0.f);
    }
}

// ---------------- launch ----------------
extern "C" void kernel_launch(void* const* d_in, const int* in_sizes, int n_in,
                              void* d_out, int out_size)
{
    const float* data = (const float*)d_in[0];
    const int*   knn  = (const int*)  d_in[1];
    const float* e1w  = (const float*)d_in[2];
    const float* e1b  = (const float*)d_in[3];
    const float* e1g  = (const float*)d_in[4];
    const float* e1be = (const float*)d_in[5];
    const float* gc1w = (const float*)d_in[6];
    const float* g1g  = (const float*)d_in[8];
    const float* g1be = (const float*)d_in[9];
    const float* gc2w = (const float*)d_in[10];
    const float* g2g  = (const float*)d_in[12];
    const float* g2be = (const float*)d_in[13];
    const float* e2w  = (const float*)d_in[14];
    const float* e2b  = (const float*)d_in[15];
    const float* e2g  = (const float*)d_in[16];
    const float* e2be = (const float*)d_in[17];
    const float* d1w  = (const float*)d_in[18];
    const float* d1b  = (const float*)d_in[19];
    const float* d1g  = (const float*)d_in[20];
    const float* d1be = (const float*)d_in[21];
    const float* d2w  = (const float*)d_in[22];
    const float* d2b  = (const float*)d_in[23];
    const float* d2g  = (const float*)d_in[24];
    const float* d2be = (const float*)d_in[25];
    float* out = (float*)d_out;

    cudaFuncSetAttribute(k_gemm1_mma, cudaFuncAttributeMaxDynamicSharedMemorySize, G1_SMEM);
    cudaFuncSetAttribute(k_gemm2_mma, cudaFuncAttributeMaxDynamicSharedMemorySize, G2_SMEM);

    k_init<<<256, 256>>>(gc1w, gc2w);
    k_cov_e1<<<MTOT/256, 256>>>(data, knn, e1w, e1b);
    k_agg1<<<MTOT/16, 256>>>(knn, e1g, e1be);
    k_gemm1_mma<<<MTOT/128, 256, G1_SMEM>>>();
    k_agg2<<<MTOT/8, 256>>>(knn, g1g, g1be);
    k_gemm2_mma<<<MTOT/128, 256, G2_SMEM>>>();
    k_fin3pool<<<BB, H1>>>(g2g, g2be);
    k_e2<<<BB, H1>>>(e2w, e2b);
    k_code2<<<1, 512>>>(e2g, e2be, d1w, d1b, d1g, d1be, d2w, d2b);
    k_decode<<<MTOT/256, 256>>>(d1w, d2w);
    k_out<<<MTOT/256, 256>>>(out, d1w, d2w, d2g, d2be);
}

// round 10
// speedup vs baseline: 1.0808x; 1.0017x over previous
#include <cuda_runtime.h>
#include <cuda_bf16.h>
#include <cstdint>

#define BB   16
#define NN   8192
#define KNB  16
#define MTOT (BB*NN)      // 131072
#define H3   64
#define H2   128
#define H1   512
#define EPSBN 1e-5f

typedef unsigned long long ull;
typedef unsigned int uint;

// ---------------- scratch ----------------
__device__ float g_pre1[MTOT*H3];
__device__ uint  g_a1hi[MTOT*32];
__device__ uint  g_a1lo[MTOT*32];
__device__ float g_pre2[MTOT*H2];
__device__ uint  g_a2hi[MTOT*64];
__device__ uint  g_a2lo[MTOT*64];
__device__ unsigned short g_w1hi[H2*H3];
__device__ unsigned short g_w1lo[H2*H3];
__device__ unsigned short g_w2hi[H1*H2];
__device__ unsigned short g_w2lo[H1*H2];
__device__ float g_sum1[H3], g_sq1[H3];
__device__ float g_sum2[H2], g_sq2[H2];
__device__ float g_sum3[H1], g_sq3[H1];
__device__ uint  g_maxk[BB*H1], g_mink[BB*H1];
__device__ float g_pre4[BB*H1];
__device__ float g_dc1[BB*3], g_dc2[BB*3];
__device__ float g_d1p[6];
__device__ float g_sumd[3], g_sqd[3];

// ---------------- helpers ----------------
__device__ __forceinline__ uint fkey(float f){
    uint u = __float_as_uint(f);
    return (u & 0x80000000u) ? ~u : (u | 0x80000000u);
}
__device__ __forceinline__ float keyf(uint k){
    uint u = (k & 0x80000000u) ? (k ^ 0x80000000u) : ~k;
    return __uint_as_float(u);
}
__device__ __forceinline__ uint smem_u32(const void* p){
    uint a; asm("{ .reg .u64 t; cvta.to.shared.u64 t, %1; cvt.u32.u64 %0, t; }" : "=r"(a) : "l"(p)); return a;
}
__device__ __forceinline__ uint pbf2(float a, float b){
    __nv_bfloat162 h = __floats2bfloat162_rn(a, b);
    return *(uint*)&h;
}
__device__ __forceinline__ void ldm4(uint* r, uint addr){
    asm volatile("ldmatrix.sync.aligned.m8n8.x4.shared.b16 {%0,%1,%2,%3}, [%4];"
        : "=r"(r[0]),"=r"(r[1]),"=r"(r[2]),"=r"(r[3]) : "r"(addr));
}
__device__ __forceinline__ void mma16816(float* d, const uint* a, uint b0, uint b1){
    asm volatile("mma.sync.aligned.m16n8k16.row.col.f32.bf16.bf16.f32 "
        "{%0,%1,%2,%3}, {%4,%5,%6,%7}, {%8,%9}, {%0,%1,%2,%3};"
        : "+f"(d[0]),"+f"(d[1]),"+f"(d[2]),"+f"(d[3])
        : "r"(a[0]),"r"(a[1]),"r"(a[2]),"r"(a[3]), "r"(b0),"r"(b1));
}

// ---------------- init: zero stats + split both weight matrices ----------------
__global__ void k_init(const float* __restrict__ w1, const float* __restrict__ w2){
    int i = blockIdx.x*blockDim.x + threadIdx.x;
    if (i < H1*H2){
        int c = i >> 7, k = i & 127;
        float v = w2[(size_t)k*H1 + c];
        __nv_bfloat16 h = __float2bfloat16_rn(v);
        float r = v - __bfloat162float(h);
        __nv_bfloat16 l = __float2bfloat16_rn(r);
        g_w2hi[i] = *(unsigned short*)&h;
        g_w2lo[i] = *(unsigned short*)&l;
    }
    if (i < H2*H3){
        int c = i >> 6, k = i & 63;
        float v = w1[(size_t)k*H2 + c];
        __nv_bfloat16 h = __float2bfloat16_rn(v);
        float r = v - __bfloat162float(h);
        __nv_bfloat16 l = __float2bfloat16_rn(r);
        g_w1hi[i] = *(unsigned short*)&h;
        g_w1lo[i] = *(unsigned short*)&l;
    }
    if (i < BB*H1){ g_maxk[i]=0u; g_mink[i]=0xFFFFFFFFu; }
    if (i < H1){ g_sum3[i]=0.f; g_sq3[i]=0.f; }
    if (i < H2){ g_sum2[i]=0.f; g_sq2[i]=0.f; }
    if (i < H3){ g_sum1[i]=0.f; g_sq1[i]=0.f; }
    if (i < 3){ g_sumd[i]=0.f; g_sqd[i]=0.f; }
}

// covariance features + Linear(12,64) + BN stats
__global__ __launch_bounds__(256) void k_cov_e1(
    const float* __restrict__ data, const int* __restrict__ knn,
    const float* __restrict__ w, const float* __restrict__ bias)
{
    __shared__ float Ws[12*H3];
    __shared__ float bs[H3];
    __shared__ float x0s[256*12];
    __shared__ float ssum[H3], ssq[H3];
    int t = threadIdx.x;
    for (int i = t; i < 12*H3; i += 256) Ws[i] = w[i];
    if (t < H3){ bs[t] = bias[t]; ssum[t]=0.f; ssq[t]=0.f; }

    int gi = blockIdx.x*256 + t;
    int b = gi >> 13;
    const int* kp = knn + (size_t)gi*KNB;
    float sx=0,sy=0,sz=0,sxx=0,sxy=0,sxz=0,syy=0,syz=0,szz=0;
    #pragma unroll
    for (int k=0;k<KNB;k++){
        int j = kp[k];
        const float* p = data + ((size_t)(b*NN + j))*3;
        float x=p[0], y=p[1], z=p[2];
        sx+=x; sy+=y; sz+=z;
        sxx+=x*x; sxy+=x*y; sxz+=x*z; syy+=y*y; syz+=y*z; szz+=z*z;
    }
    float mx=sx*(1.f/16.f), my=sy*(1.f/16.f), mz=sz*(1.f/16.f);
    const float i15 = 1.f/15.f;
    float cxx=(sxx-16.f*mx*mx)*i15, cxy=(sxy-16.f*mx*my)*i15, cxz=(sxz-16.f*mx*mz)*i15;
    float cyy=(syy-16.f*my*my)*i15, cyz=(syz-16.f*my*mz)*i15, czz=(szz-16.f*mz*mz)*i15;
    float* xr = &x0s[t*12];
    xr[0]=data[(size_t)gi*3+0]; xr[1]=data[(size_t)gi*3+1]; xr[2]=data[(size_t)gi*3+2];
    xr[3]=cxx; xr[4]=cxy; xr[5]=cxz; xr[6]=cxy; xr[7]=cyy; xr[8]=cyz; xr[9]=cxz; xr[10]=cyz; xr[11]=czz;
    __syncthreads();

    int c = t & 63;
    float bsum=0.f, bsq=0.f;
    float* outp = g_pre1 + (size_t)blockIdx.x*256*H3;
    #pragma unroll 4
    for (int kq=0;kq<64;kq++){
        int e = t + kq*256;
        const float* x0 = &x0s[(e>>6)*12];
        float v = bs[c];
        #pragma unroll
        for (int j=0;j<12;j++) v = fmaf(x0[j], Ws[j*H3+c], v);
        outp[e] = v;
        bsum += v; bsq += v*v;
    }
    atomicAdd(&ssum[c], bsum); atomicAdd(&ssq[c], bsq);
    __syncthreads();
    if (t < H3){ atomicAdd(&g_sum1[t], ssum[t]); atomicAdd(&g_sq1[t], ssq[t]); }
}

// layer1 agg: inline BN + ReLU gather, /17 -> bf16 hi/lo
__global__ __launch_bounds__(256) void k_agg1(const int* __restrict__ knn,
    const float* __restrict__ eg, const float* __restrict__ ebe){
    const int TPN = H3/4;         // 16
    const int NPB = 256/TPN;      // 16
    __shared__ int sidx[NPB][KNB];
    int t = threadIdx.x;
    int n0 = blockIdx.x*NPB;
    if (t < NPB*KNB) sidx[t>>4][t&15] = knn[(size_t)(n0 + (t>>4))*KNB + (t&15)];
    __syncthreads();
    int nl = t / TPN; int c4 = t % TPN;
    int gi = n0 + nl;
    int base = (gi >> 13) * NN;
    const float4* pre = (const float4*)g_pre1;
    float4 sc, sh;
    {
        const float invM = 1.f/(float)MTOT;
        float m, v, s;
        int c = c4*4;
        m = g_sum1[c]*invM;   v = fmaxf(g_sq1[c]*invM - m*m, 0.f);   s = eg[c]*rsqrtf(v+EPSBN);   sc.x=s; sh.x=fmaf(-m,s,ebe[c]);
        m = g_sum1[c+1]*invM; v = fmaxf(g_sq1[c+1]*invM - m*m, 0.f); s = eg[c+1]*rsqrtf(v+EPSBN); sc.y=s; sh.y=fmaf(-m,s,ebe[c+1]);
        m = g_sum1[c+2]*invM; v = fmaxf(g_sq1[c+2]*invM - m*m, 0.f); s = eg[c+2]*rsqrtf(v+EPSBN); sc.z=s; sh.z=fmaf(-m,s,ebe[c+2]);
        m = g_sum1[c+3]*invM; v = fmaxf(g_sq1[c+3]*invM - m*m, 0.f); s = eg[c+3]*rsqrtf(v+EPSBN); sc.w=s; sh.w=fmaf(-m,s,ebe[c+3]);
    }
    float4 p = pre[(size_t)gi*TPN + c4];
    float ax = fmaxf(fmaf(p.x, sc.x, sh.x), 0.f);
    float ay = fmaxf(fmaf(p.y, sc.y, sh.y), 0.f);
    float az = fmaxf(fmaf(p.z, sc.z, sh.z), 0.f);
    float aw = fmaxf(fmaf(p.w, sc.w, sh.w), 0.f);
    #pragma unroll
    for (int k=0;k<KNB;k++){
        int nb = base + sidx[nl][k];
        float4 q = pre[(size_t)nb*TPN + c4];
        ax += fmaxf(fmaf(q.x, sc.x, sh.x), 0.f);
        ay += fmaxf(fmaf(q.y, sc.y, sh.y), 0.f);
        az += fmaxf(fmaf(q.z, sc.z, sh.z), 0.f);
        aw += fmaxf(fmaf(q.w, sc.w, sh.w), 0.f);
    }
    const float s = 1.f/17.f;
    ax*=s; ay*=s; az*=s; aw*=s;
    __nv_bfloat162 h01 = __floats2bfloat162_rn(ax, ay);
    __nv_bfloat162 h23 = __floats2bfloat162_rn(az, aw);
    size_t o = (size_t)gi*32 + c4*2;
    g_a1hi[o]   = *(uint*)&h01;
    g_a1hi[o+1] = *(uint*)&h23;
    g_a1lo[o]   = pbf2(ax - __bfloat162float(h01.x), ay - __bfloat162float(h01.y));
    g_a1lo[o+1] = pbf2(az - __bfloat162float(h23.x), aw - __bfloat162float(h23.y));
}

// layer2 agg: inline BN + ReLU gather, /17 -> bf16 hi/lo
__global__ __launch_bounds__(256) void k_agg2(const int* __restrict__ knn,
    const float* __restrict__ gg, const float* __restrict__ gbe){
    const int TPN = H2/4;         // 32
    const int NPB = 256/TPN;      // 8
    __shared__ int sidx[NPB][KNB];
    int t = threadIdx.x;
    int n0 = blockIdx.x*NPB;
    if (t < NPB*KNB) sidx[t>>4][t&15] = knn[(size_t)(n0 + (t>>4))*KNB + (t&15)];
    __syncthreads();
    int nl = t / TPN; int c4 = t % TPN;
    int gi = n0 + nl;
    int base = (gi >> 13) * NN;
    const float4* pre = (const float4*)g_pre2;
    float4 sc, sh;
    {
        const float invM = 1.f/(float)MTOT;
        float m, v, s;
        int c = c4*4;
        m = g_sum2[c]*invM;   v = fmaxf(g_sq2[c]*invM - m*m, 0.f);   s = gg[c]*rsqrtf(v+EPSBN);   sc.x=s; sh.x=fmaf(-m,s,gbe[c]);
        m = g_sum2[c+1]*invM; v = fmaxf(g_sq2[c+1]*invM - m*m, 0.f); s = gg[c+1]*rsqrtf(v+EPSBN); sc.y=s; sh.y=fmaf(-m,s,gbe[c+1]);
        m = g_sum2[c+2]*invM; v = fmaxf(g_sq2[c+2]*invM - m*m, 0.f); s = gg[c+2]*rsqrtf(v+EPSBN); sc.z=s; sh.z=fmaf(-m,s,gbe[c+2]);
        m = g_sum2[c+3]*invM; v = fmaxf(g_sq2[c+3]*invM - m*m, 0.f); s = gg[c+3]*rsqrtf(v+EPSBN); sc.w=s; sh.w=fmaf(-m,s,gbe[c+3]);
    }
    float4 p = pre[(size_t)gi*TPN + c4];
    float ax = fmaxf(fmaf(p.x, sc.x, sh.x), 0.f);
    float ay = fmaxf(fmaf(p.y, sc.y, sh.y), 0.f);
    float az = fmaxf(fmaf(p.z, sc.z, sh.z), 0.f);
    float aw = fmaxf(fmaf(p.w, sc.w, sh.w), 0.f);
    #pragma unroll
    for (int k=0;k<KNB;k++){
        int nb = base + sidx[nl][k];
        float4 q = pre[(size_t)nb*TPN + c4];
        ax += fmaxf(fmaf(q.x, sc.x, sh.x), 0.f);
        ay += fmaxf(fmaf(q.y, sc.y, sh.y), 0.f);
        az += fmaxf(fmaf(q.z, sc.z, sh.z), 0.f);
        aw += fmaxf(fmaf(q.w, sc.w, sh.w), 0.f);
    }
    const float s = 1.f/17.f;
    ax*=s; ay*=s; az*=s; aw*=s;
    __nv_bfloat162 h01 = __floats2bfloat162_rn(ax, ay);
    __nv_bfloat162 h23 = __floats2bfloat162_rn(az, aw);
    size_t o = (size_t)gi*64 + c4*2;
    g_a2hi[o]   = *(uint*)&h01;
    g_a2hi[o+1] = *(uint*)&h23;
    g_a2lo[o]   = pbf2(ax - __bfloat162float(h01.x), ay - __bfloat162float(h01.y));
    g_a2lo[o+1] = pbf2(az - __bfloat162float(h23.x), aw - __bfloat162float(h23.y));
}

// ---------------- gemm1: mma bf16 split (128 nodes x 128 cols, K=64) ----------------
#define AH1_OFF 0u
#define AL1_OFF 18432u
#define BH1_OFF 36864u
#define BL1_OFF 55296u
#define S1SUM_OFF 73728u
#define S1SQ_OFF  74240u
#define G1_SMEM   74752

__global__ void __launch_bounds__(256) k_gemm1_mma(){
    extern __shared__ __align__(16) char sm[];
    uint sb = smem_u32(sm);
    int t = threadIdx.x, lane = t & 31, wid = t >> 5;
    int wm = wid >> 2, wn = wid & 3;
    int node0 = blockIdx.x*128;

    float* ssum = (float*)(sm + S1SUM_OFF);
    float* ssq  = (float*)(sm + S1SQ_OFF);

    {
        int row = t >> 1, half = t & 1;
        const uint4* ph = (const uint4*)(g_a1hi + (size_t)(node0+row)*32) + half*4;
        const uint4* pl = (const uint4*)(g_a1lo + (size_t)(node0+row)*32) + half*4;
        uint4* dh = (uint4*)(sm + AH1_OFF + row*144 + half*64);
        uint4* dl = (uint4*)(sm + AL1_OFF + row*144 + half*64);
        #pragma unroll
        for (int i=0;i<4;i++){ dh[i] = ph[i]; dl[i] = pl[i]; }
    }
    {
        int col = t >> 1, half = t & 1;
        const uint4* ph = (const uint4*)((const char*)g_w1hi + (size_t)col*128) + half*4;
        const uint4* pl = (const uint4*)((const char*)g_w1lo + (size_t)col*128) + half*4;
        uint4* dh = (uint4*)(sm + BH1_OFF + col*144 + half*64);
        uint4* dl = (uint4*)(sm + BL1_OFF + col*144 + half*64);
        #pragma unroll
        for (int i=0;i<4;i++){ dh[i] = ph[i]; dl[i] = pl[i]; }
    }
    if (t < 128){ ssum[t]=0.f; ssq[t]=0.f; }
    __syncthreads();

    uint aBase = sb + AH1_OFF + (uint)((wm*64 + (lane & 15))*144 + (lane >> 4)*16);
    uint bBase = sb + BH1_OFF + (uint)((wn*32 + (lane & 7) + ((lane >> 4) & 1)*8)*144 + ((lane >> 3) & 1)*16);

    float acc[4][4][4];
    #pragma unroll
    for (int mi=0;mi<4;mi++)
        #pragma unroll
        for (int j=0;j<4;j++)
            #pragma unroll
            for (int r=0;r<4;r++) acc[mi][j][r] = 0.f;

    #pragma unroll
    for (int ks=0; ks<4; ks++){
        uint bh[8], bl[8];
        ldm4(bh,   bBase + ks*32);
        ldm4(bh+4, bBase + 16*144 + ks*32);
        ldm4(bl,   bBase + (BL1_OFF-BH1_OFF) + ks*32);
        ldm4(bl+4, bBase + (BL1_OFF-BH1_OFF) + 16*144 + ks*32);
        #pragma unroll
        for (int mi=0; mi<4; mi++){
            uint ah[4], al[4];
            ldm4(ah, aBase + mi*16*144 + ks*32);
            ldm4(al, aBase + (AL1_OFF-AH1_OFF) + mi*16*144 + ks*32);
            #pragma unroll
            for (int j=0;j<4;j++){
                mma16816(acc[mi][j], ah, bh[2*j], bh[2*j+1]);
                mma16816(acc[mi][j], al, bh[2*j], bh[2*j+1]);
                mma16816(acc[mi][j], ah, bl[2*j], bl[2*j+1]);
            }
        }
    }

    #pragma unroll
    for (int mi=0;mi<4;mi++){
        int r0 = node0 + wm*64 + mi*16 + (lane >> 2);
        #pragma unroll
        for (int j=0;j<4;j++){
            int c0 = wn*32 + j*8 + (lane & 3)*2;
            *(float2*)&g_pre2[(size_t)r0*H2 + c0]     = make_float2(acc[mi][j][0], acc[mi][j][1]);
            *(float2*)&g_pre2[(size_t)(r0+8)*H2 + c0] = make_float2(acc[mi][j][2], acc[mi][j][3]);
        }
    }
    #pragma unroll
    for (int j=0;j<4;j++){
        #pragma unroll
        for (int p=0;p<2;p++){
            float s=0.f, qq=0.f;
            #pragma unroll
            for (int mi=0;mi<4;mi++){
                #pragma unroll
                for (int r=0;r<2;r++){
                    float v = acc[mi][j][2*r+p];
                    s += v; qq = fmaf(v, v, qq);
                }
            }
            #pragma unroll
            for (int o=4;o<32;o<<=1){
                s  += __shfl_xor_sync(0xffffffffu, s, o);
                qq += __shfl_xor_sync(0xffffffffu, qq, o);
            }
            if (lane < 4){
                int colq = wn*32 + j*8 + lane*2 + p;
                atomicAdd(&ssum[colq], s);
                atomicAdd(&ssq[colq], qq);
            }
        }
    }
    __syncthreads();
    if (t < 128){
        atomicAdd(&g_sum2[t], ssum[t]);
        atomicAdd(&g_sq2[t], ssq[t]);
    }
}

// ---------------- gemm2: mma bf16 split (128 nodes x 512 cols, K=128) — R7 single-pass ----------------
#define AH_OFF 0u
#define AL_OFF 34816u
#define BH_OFF 69632u
#define BL_OFF 104448u
#define SSUM_OFF 139264u
#define SSQ_OFF  139776u
#define SMX_OFF  140288u
#define SMN_OFF  140800u
#define G2_SMEM  141312

__global__ void __launch_bounds__(256) k_gemm2_mma(){
    extern __shared__ __align__(16) char sm[];
    uint sb = smem_u32(sm);
    int t = threadIdx.x, lane = t & 31, wid = t >> 5;
    int wm = wid >> 2, wn = wid & 3;
    int node0 = blockIdx.x*128;
    int batch = blockIdx.x >> 6;

    float* ssum = (float*)(sm + SSUM_OFF);
    float* ssq  = (float*)(sm + SSQ_OFF);
    uint*  smx  = (uint*)(sm + SMX_OFF);
    uint*  smn  = (uint*)(sm + SMN_OFF);

    {
        int row = t >> 1, half = t & 1;
        const uint4* ph = (const uint4*)(g_a2hi + (size_t)(node0+row)*64) + half*8;
        const uint4* pl = (const uint4*)(g_a2lo + (size_t)(node0+row)*64) + half*8;
        uint4* dh = (uint4*)(sm + AH_OFF + row*272 + half*128);
        uint4* dl = (uint4*)(sm + AL_OFF + row*272 + half*128);
        #pragma unroll
        for (int i=0;i<8;i++){ dh[i] = ph[i]; dl[i] = pl[i]; }
    }

    uint aBase = sb + AH_OFF + (uint)((wm*64 + (lane & 15))*272 + (lane >> 4)*16);
    uint bBase = sb + BH_OFF + (uint)((wn*32 + (lane & 7) + ((lane >> 4) & 1)*8)*272 + ((lane >> 3) & 1)*16);

    for (int q = 0; q < 4; q++){
        int cb = q*128;
        {
            int col = t >> 1, half = t & 1;
            const uint4* ph = (const uint4*)((const char*)g_w2hi + (size_t)(cb+col)*256) + half*8;
            const uint4* pl = (const uint4*)((const char*)g_w2lo + (size_t)(cb+col)*256) + half*8;
            uint4* dh = (uint4*)(sm + BH_OFF + col*272 + half*128);
            uint4* dl = (uint4*)(sm + BL_OFF + col*272 + half*128);
            #pragma unroll
            for (int i=0;i<8;i++){ dh[i] = ph[i]; dl[i] = pl[i]; }
        }
        if (t < 128){ ssum[t]=0.f; ssq[t]=0.f; smx[t]=0u; smn[t]=0xFFFFFFFFu; }
        __syncthreads();

        float acc[4][4][4];
        #pragma unroll
        for (int mi=0;mi<4;mi++)
            #pragma unroll
            for (int j=0;j<4;j++)
                #pragma unroll
                for (int r=0;r<4;r++) acc[mi][j][r] = 0.f;

        #pragma unroll
        for (int ks=0; ks<8; ks++){
            uint bh[8], bl[8];
            ldm4(bh,   bBase + ks*32);
            ldm4(bh+4, bBase + 16*272 + ks*32);
            ldm4(bl,   bBase + (BL_OFF-BH_OFF) + ks*32);
            ldm4(bl+4, bBase + (BL_OFF-BH_OFF) + 16*272 + ks*32);
            #pragma unroll
            for (int mi=0; mi<4; mi++){
                uint ah[4], al[4];
                ldm4(ah, aBase + mi*16*272 + ks*32);
                ldm4(al, aBase + (AL_OFF-AH_OFF) + mi*16*272 + ks*32);
                #pragma unroll
                for (int j=0;j<4;j++){
                    mma16816(acc[mi][j], ah, bh[2*j], bh[2*j+1]);
                    mma16816(acc[mi][j], al, bh[2*j], bh[2*j+1]);
                    mma16816(acc[mi][j], ah, bl[2*j], bl[2*j+1]);
                }
            }
        }

        #pragma unroll
        for (int j=0;j<4;j++){
            #pragma unroll
            for (int p=0;p<2;p++){
                float s=0.f, qq=0.f, mx=-3.402823466e38f, mn=3.402823466e38f;
                #pragma unroll
                for (int mi=0;mi<4;mi++){
                    #pragma unroll
                    for (int r=0;r<2;r++){
                        float v = acc[mi][j][2*r+p];
                        s += v; qq = fmaf(v, v, qq);
                        mx = fmaxf(mx, v); mn = fminf(mn, v);
                    }
                }
                #pragma unroll
                for (int o=4;o<32;o<<=1){
                    s  += __shfl_xor_sync(0xffffffffu, s, o);
                    qq += __shfl_xor_sync(0xffffffffu, qq, o);
                    mx = fmaxf(mx, __shfl_xor_sync(0xffffffffu, mx, o));
                    mn = fminf(mn, __shfl_xor_sync(0xffffffffu, mn, o));
                }
                if (lane < 4){
                    int colq = wn*32 + j*8 + lane*2 + p;
                    atomicAdd(&ssum[colq], s);
                    atomicAdd(&ssq[colq], qq);
                    atomicMax(&smx[colq], fkey(mx));
                    atomicMin(&smn[colq], fkey(mn));
                }
            }
        }
        __syncthreads();
        if (t < 128){
            atomicAdd(&g_sum3[cb+t], ssum[t]);
            atomicAdd(&g_sq3[cb+t], ssq[t]);
            atomicMax(&g_maxk[batch*H1 + cb + t], smx[t]);
            atomicMin(&g_mink[batch*H1 + cb + t], smn[t]);
        }
        __syncthreads();
    }
}

// e2 linear fused with BN3-pool: block per batch
__global__ __launch_bounds__(512) void k_e2(
    const float* __restrict__ g, const float* __restrict__ be,
    const float* __restrict__ W, const float* __restrict__ bias)
{
    __shared__ float sp[H1];
    int b = blockIdx.x, c = threadIdx.x;
    {
        float invM = 1.f/(float)MTOT;
        float s = g_sum3[c]*invM;
        float q = g_sq3[c]*invM;
        float v = fmaxf(q - s*s, 0.f);
        float sc = g[c]*rsqrtf(v+EPSBN);
        float sh = fmaf(-s, sc, be[c]);
        float mx = keyf(g_maxk[b*H1+c]);
        float mn = keyf(g_mink[b*H1+c]);
        float val = (sc >= 0.f) ? fmaf(mx, sc, sh) : fmaf(mn, sc, sh);
        sp[c] = fmaxf(val, 0.f);
    }
    __syncthreads();
    float acc = bias[c];
    #pragma unroll 4
    for (int f=0; f<H1; f++) acc = fmaf(sp[f], W[(size_t)f*H1 + c], acc);
    g_pre4[b*H1 + c] = acc;
}

// e2 BN(M=16)+ReLU -> code; decoder per-batch dots; analytic d1 BN params
__global__ __launch_bounds__(512) void k_code2(
    const float* __restrict__ eg, const float* __restrict__ ebe,
    const float* __restrict__ d1w, const float* __restrict__ d1b,
    const float* __restrict__ d1g, const float* __restrict__ d1be,
    const float* __restrict__ d2w, const float* __restrict__ d2b)
{
    __shared__ float scm[BB*H1];
    int t = threadIdx.x;
    float vals[16]; float s = 0.f;
    #pragma unroll
    for (int b=0;b<16;b++){ vals[b]=g_pre4[b*H1+t]; s+=vals[b]; }
    float m = s*(1.f/16.f);
    float q = 0.f;
    #pragma unroll
    for (int b=0;b<16;b++){ float d=vals[b]-m; q+=d*d; }
    float scl = eg[t]*rsqrtf(q*(1.f/16.f)+EPSBN);
    float sh = ebe[t];
    #pragma unroll
    for (int b=0;b<16;b++) scm[b*H1+t] = fmaxf(fmaf(vals[b]-m, scl, sh), 0.f);
    __syncthreads();

    int w = t>>5, lane = t&31;
    if (w < 6){
        for (int d = w*16; d < w*16+16; d++){
            int layer = d/48; int r = d%48; int b = r/3; int c = r%3;
            const float* Wd = layer ? d2w : d1w;
            float p = 0.f;
            for (int f=lane; f<H1; f+=32) p = fmaf(scm[b*H1+f], Wd[f*3+c], p);
            #pragma unroll
            for (int o=16;o;o>>=1) p += __shfl_xor_sync(0xffffffffu, p, o);
            if (lane==0){
                if (layer) g_dc2[b*3+c] = p + d2b[c];
                else       g_dc1[b*3+c] = p + d1b[c];
            }
        }
    }
    __syncthreads();
    if (w < 3){
        float wx = d1w[1536 + w], wy = d1w[1539 + w];
        float sG = 0.f;
        for (int n=lane; n<NN; n+=32){
            int ix = n/65, iy = n - ix*65;
            float gx = 1.f + ix*(119.f/128.f);
            float gy = 1.f + iy*(59.f/64.f);
            sG += gx*wx + gy*wy;
        }
        #pragma unroll
        for (int o=16;o;o>>=1) sG += __shfl_xor_sync(0xffffffffu, sG, o);
        float mG = sG*(1.f/8192.f);
        float qG = 0.f;
        for (int n=lane; n<NN; n+=32){
            int ix = n/65, iy = n - ix*65;
            float gx = 1.f + ix*(119.f/128.f);
            float gy = 1.f + iy*(59.f/64.f);
            float d = gx*wx + gy*wy - mG;
            qG += d*d;
        }
        #pragma unroll
        for (int o=16;o;o>>=1) qG += __shfl_xor_sync(0xffffffffu, qG, o);
        if (lane==0){
            float vG = qG*(1.f/8192.f);
            float sA=0.f;
            #pragma unroll
            for (int b=0;b<16;b++) sA += g_dc1[b*3+w];
            float mA = sA*(1.f/16.f);
            float qA=0.f;
            #pragma unroll
            for (int b=0;b<16;b++){ float d=g_dc1[b*3+w]-mA; qA+=d*d; }
            float vA = qA*(1.f/16.f);
            float mean = mA + mG;
            float var = fmaxf(vA + vG, 0.f);
            float sc1 = d1g[w]*rsqrtf(var+EPSBN);
            g_d1p[w]=sc1; g_d1p[3+w]= d1be[w] - mean*sc1;
        }
    }
}

// decode stats only
__global__ __launch_bounds__(256) void k_decode(const float* __restrict__ d1w, const float* __restrict__ d2w){
    __shared__ float ss[3], sq_[3];
    int t = threadIdx.x;
    if (t<3){ ss[t]=0.f; sq_[t]=0.f; }
    __syncthreads();
    int gi = blockIdx.x*256 + t;
    int n = gi & (NN-1);
    int b = gi >> 13;
    int ix = n/65, iy = n - ix*65;
    float gx = 1.f + ix*(119.f/128.f);
    float gy = 1.f + iy*(59.f/64.f);
    float z1[3];
    #pragma unroll
    for (int c=0;c<3;c++){
        float pre = g_dc1[b*3+c] + gx*d1w[1536+c] + gy*d1w[1539+c];
        z1[c] = fmaxf(fmaf(pre, g_d1p[c], g_d1p[3+c]), 0.f);
    }
    int lane = t & 31;
    #pragma unroll
    for (int c=0;c<3;c++){
        float v = g_dc2[b*3+c] + z1[0]*d2w[1536+c] + z1[1]*d2w[1539+c] + z1[2]*d2w[1542+c];
        float sv = v, qv = v*v;
        #pragma unroll
        for (int o=16;o;o>>=1){ sv += __shfl_xor_sync(0xffffffffu, sv, o); qv += __shfl_xor_sync(0xffffffffu, qv, o); }
        if (lane==0){ atomicAdd(&ss[c], sv); atomicAdd(&sq_[c], qv); }
    }
    __syncthreads();
    if (t<3){ atomicAdd(&g_sumd[t], ss[t]); atomicAdd(&g_sqd[t], sq_[t]); }
}

// out: recompute decoder output analytically + final BN+ReLU
__global__ __launch_bounds__(256) void k_out(
    float* __restrict__ out, const float* __restrict__ d1w, const float* __restrict__ d2w,
    const float* __restrict__ g, const float* __restrict__ be)
{
    int gi = blockIdx.x*256 + threadIdx.x;
    int n = gi & (NN-1);
    int b = gi >> 13;
    int ix = n/65, iy = n - ix*65;
    float gx = 1.f + ix*(119.f/128.f);
    float gy = 1.f + iy*(59.f/64.f);
    float z1[3];
    #pragma unroll
    for (int c=0;c<3;c++){
        float pre = g_dc1[b*3+c] + gx*d1w[1536+c] + gy*d1w[1539+c];
        z1[c] = fmaxf(fmaf(pre, g_d1p[c], g_d1p[3+c]), 0.f);
    }
    float invM = 1.f/(float)MTOT;
    #pragma unroll
    for (int c=0;c<3;c++){
        float v = g_dc2[b*3+c] + z1[0]*d2w[1536+c] + z1[1]*d2w[1539+c] + z1[2]*d2w[1542+c];
        float m = g_sumd[c]*invM;
        float var = fmaxf(g_sqd[c]*invM - m*m, 0.f);
        float sc = g[c]*rsqrtf(var+EPSBN);
        out[(size_t)gi*3 + c] = fmaxf(fmaf(v-m, sc, be[c]), 0.f);
    }
}

// ---------------- launch ----------------
extern "C" void kernel_launch(void* const* d_in, const int* in_sizes, int n_in,
                              void* d_out, int out_size)
{
    const float* data = (const float*)d_in[0];
    const int*   knn  = (const int*)  d_in[1];
    const float* e1w  = (const float*)d_in[2];
    const float* e1b  = (const float*)d_in[3];
    const float* e1g  = (const float*)d_in[4];
    const float* e1be = (const float*)d_in[5];
    const float* gc1w = (const float*)d_in[6];
    const float* g1g  = (const float*)d_in[8];
    const float* g1be = (const float*)d_in[9];
    const float* gc2w = (const float*)d_in[10];
    const float* g2g  = (const float*)d_in[12];
    const float* g2be = (const float*)d_in[13];
    const float* e2w  = (const float*)d_in[14];
    const float* e2b  = (const float*)d_in[15];
    const float* e2g  = (const float*)d_in[16];
    const float* e2be = (const float*)d_in[17];
    const float* d1w  = (const float*)d_in[18];
    const float* d1b  = (const float*)d_in[19];
    const float* d1g  = (const float*)d_in[20];
    const float* d1be = (const float*)d_in[21];
    const float* d2w  = (const float*)d_in[22];
    const float* d2b  = (const float*)d_in[23];
    const float* d2g  = (const float*)d_in[24];
    const float* d2be = (const float*)d_in[25];
    float* out = (float*)d_out;

    cudaFuncSetAttribute(k_gemm1_mma, cudaFuncAttributeMaxDynamicSharedMemorySize, G1_SMEM);
    cudaFuncSetAttribute(k_gemm2_mma, cudaFuncAttributeMaxDynamicSharedMemorySize, G2_SMEM);

    k_init<<<256, 256>>>(gc1w, gc2w);
    k_cov_e1<<<MTOT/256, 256>>>(data, knn, e1w, e1b);
    k_agg1<<<MTOT/16, 256>>>(knn, e1g, e1be);
    k_gemm1_mma<<<MTOT/128, 256, G1_SMEM>>>();
    k_agg2<<<MTOT/8, 256>>>(knn, g1g, g1be);
    k_gemm2_mma<<<MTOT/128, 256, G2_SMEM>>>();
    k_e2<<<BB, H1>>>(g2g, g2be, e2w, e2b);
    k_code2<<<1, 512>>>(e2g, e2be, d1w, d1b, d1g, d1be, d2w, d2b);
    k_decode<<<MTOT/256, 256>>>(d1w, d2w);
    k_out<<<MTOT/256, 256>>>(out, d1w, d2w, d2g, d2be);
}

// round 11
// speedup vs baseline: 1.2434x; 1.1504x over previous
#include <cuda_runtime.h>
#include <cuda_bf16.h>
#include <cstdint>

#define BB   16
#define NN   8192
#define KNB  16
#define MTOT (BB*NN)      // 131072
#define H3   64
#define H2   128
#define H1   512
#define EPSBN 1e-5f

typedef unsigned long long ull;
typedef unsigned int uint;

// ---------------- scratch ----------------
__device__ float g_pre1[MTOT*H3];
__device__ uint  g_a1hi[MTOT*32];
__device__ uint  g_a1lo[MTOT*32];
__device__ float g_pre2[MTOT*H2];
__device__ uint  g_a2hi[MTOT*64];
__device__ uint  g_a2lo[MTOT*64];
__device__ unsigned short g_w1hi[H2*H3];
__device__ unsigned short g_w1lo[H2*H3];
__device__ unsigned short g_w2hi[H1*H2];
__device__ unsigned short g_w2lo[H1*H2];
__device__ float g_sum1[H3], g_sq1[H3];
__device__ float g_sum2[H2], g_sq2[H2];
__device__ float g_sum3[H1], g_sq3[H1];
__device__ uint  g_maxk[BB*H1], g_mink[BB*H1];
__device__ float g_bn1[2*H3];
__device__ float g_bn2[2*H2];
__device__ float g_pre4[BB*H1];
__device__ float g_dc1[BB*3], g_dc2[BB*3];
__device__ float g_d1p[6];
__device__ float g_sumd[3], g_sqd[3];

// ---------------- helpers ----------------
__device__ __forceinline__ uint fkey(float f){
    uint u = __float_as_uint(f);
    return (u & 0x80000000u) ? ~u : (u | 0x80000000u);
}
__device__ __forceinline__ float keyf(uint k){
    uint u = (k & 0x80000000u) ? (k ^ 0x80000000u) : ~k;
    return __uint_as_float(u);
}
__device__ __forceinline__ uint smem_u32(const void* p){
    uint a; asm("{ .reg .u64 t; cvta.to.shared.u64 t, %1; cvt.u32.u64 %0, t; }" : "=r"(a) : "l"(p)); return a;
}
__device__ __forceinline__ uint pbf2(float a, float b){
    __nv_bfloat162 h = __floats2bfloat162_rn(a, b);
    return *(uint*)&h;
}
__device__ __forceinline__ void ldm4(uint* r, uint addr){
    asm volatile("ldmatrix.sync.aligned.m8n8.x4.shared.b16 {%0,%1,%2,%3}, [%4];"
        : "=r"(r[0]),"=r"(r[1]),"=r"(r[2]),"=r"(r[3]) : "r"(addr));
}
__device__ __forceinline__ void mma16816(float* d, const uint* a, uint b0, uint b1){
    asm volatile("mma.sync.aligned.m16n8k16.row.col.f32.bf16.bf16.f32 "
        "{%0,%1,%2,%3}, {%4,%5,%6,%7}, {%8,%9}, {%0,%1,%2,%3};"
        : "+f"(d[0]),"+f"(d[1]),"+f"(d[2]),"+f"(d[3])
        : "r"(a[0]),"r"(a[1]),"r"(a[2]),"r"(a[3]), "r"(b0),"r"(b1));
}

// ---------------- init: zero stats + split both weight matrices ----------------
__global__ void k_init(const float* __restrict__ w1, const float* __restrict__ w2){
    int i = blockIdx.x*blockDim.x + threadIdx.x;
    if (i < H1*H2){
        int c = i >> 7, k = i & 127;
        float v = w2[(size_t)k*H1 + c];
        __nv_bfloat16 h = __float2bfloat16_rn(v);
        float r = v - __bfloat162float(h);
        __nv_bfloat16 l = __float2bfloat16_rn(r);
        g_w2hi[i] = *(unsigned short*)&h;
        g_w2lo[i] = *(unsigned short*)&l;
    }
    if (i < H2*H3){
        int c = i >> 6, k = i & 63;
        float v = w1[(size_t)k*H2 + c];
        __nv_bfloat16 h = __float2bfloat16_rn(v);
        float r = v - __bfloat162float(h);
        __nv_bfloat16 l = __float2bfloat16_rn(r);
        g_w1hi[i] = *(unsigned short*)&h;
        g_w1lo[i] = *(unsigned short*)&l;
    }
    if (i < BB*H1){ g_maxk[i]=0u; g_mink[i]=0xFFFFFFFFu; }
    if (i < H1){ g_sum3[i]=0.f; g_sq3[i]=0.f; }
    if (i < H2){ g_sum2[i]=0.f; g_sq2[i]=0.f; }
    if (i < H3){ g_sum1[i]=0.f; g_sq1[i]=0.f; }
    if (i < 3){ g_sumd[i]=0.f; g_sqd[i]=0.f; }
}

// covariance features + Linear(12,64) + BN stats
__global__ __launch_bounds__(256) void k_cov_e1(
    const float* __restrict__ data, const int* __restrict__ knn,
    const float* __restrict__ w, const float* __restrict__ bias)
{
    __shared__ float Ws[12*H3];
    __shared__ float bs[H3];
    __shared__ float x0s[256*12];
    __shared__ float ssum[H3], ssq[H3];
    int t = threadIdx.x;
    for (int i = t; i < 12*H3; i += 256) Ws[i] = w[i];
    if (t < H3){ bs[t] = bias[t]; ssum[t]=0.f; ssq[t]=0.f; }

    int gi = blockIdx.x*256 + t;
    int b = gi >> 13;
    const int* kp = knn + (size_t)gi*KNB;
    float sx=0,sy=0,sz=0,sxx=0,sxy=0,sxz=0,syy=0,syz=0,szz=0;
    #pragma unroll
    for (int k=0;k<KNB;k++){
        int j = kp[k];
        const float* p = data + ((size_t)(b*NN + j))*3;
        float x=p[0], y=p[1], z=p[2];
        sx+=x; sy+=y; sz+=z;
        sxx+=x*x; sxy+=x*y; sxz+=x*z; syy+=y*y; syz+=y*z; szz+=z*z;
    }
    float mx=sx*(1.f/16.f), my=sy*(1.f/16.f), mz=sz*(1.f/16.f);
    const float i15 = 1.f/15.f;
    float cxx=(sxx-16.f*mx*mx)*i15, cxy=(sxy-16.f*mx*my)*i15, cxz=(sxz-16.f*mx*mz)*i15;
    float cyy=(syy-16.f*my*my)*i15, cyz=(syz-16.f*my*mz)*i15, czz=(szz-16.f*mz*mz)*i15;
    float* xr = &x0s[t*12];
    xr[0]=data[(size_t)gi*3+0]; xr[1]=data[(size_t)gi*3+1]; xr[2]=data[(size_t)gi*3+2];
    xr[3]=cxx; xr[4]=cxy; xr[5]=cxz; xr[6]=cxy; xr[7]=cyy; xr[8]=cyz; xr[9]=cxz; xr[10]=cyz; xr[11]=czz;
    __syncthreads();

    int c = t & 63;
    float bsum=0.f, bsq=0.f;
    float* outp = g_pre1 + (size_t)blockIdx.x*256*H3;
    #pragma unroll 4
    for (int kq=0;kq<64;kq++){
        int e = t + kq*256;
        const float* x0 = &x0s[(e>>6)*12];
        float v = bs[c];
        #pragma unroll
        for (int j=0;j<12;j++) v = fmaf(x0[j], Ws[j*H3+c], v);
        outp[e] = v;
        bsum += v; bsq += v*v;
    }
    atomicAdd(&ssum[c], bsum); atomicAdd(&ssq[c], bsq);
    __syncthreads();
    if (t < H3){ atomicAdd(&g_sum1[t], ssum[t]); atomicAdd(&g_sq1[t], ssq[t]); }
}

template<int C, int LAYER>
__global__ void k_fin(const float* __restrict__ g, const float* __restrict__ be){
    int c = threadIdx.x;
    const float* su = (LAYER==1)? g_sum1 : g_sum2;
    const float* sq = (LAYER==1)? g_sq1  : g_sq2;
    float* bn = (LAYER==1)? g_bn1 : g_bn2;
    float invM = 1.f/(float)MTOT;
    float m = su[c]*invM;
    float v = fmaxf(sq[c]*invM - m*m, 0.f);
    float sc = g[c]*rsqrtf(v+EPSBN);
    bn[c]=sc; bn[C+c]= fmaf(-m, sc, be[c]);
}

// layer1 agg: BN+ReLU on the fly, /17 -> bf16 hi/lo
__global__ __launch_bounds__(256) void k_agg1(const int* __restrict__ knn){
    const int TPN = H3/4;         // 16
    const int NPB = 256/TPN;      // 16
    __shared__ int sidx[NPB][KNB];
    int t = threadIdx.x;
    int n0 = blockIdx.x*NPB;
    if (t < NPB*KNB) sidx[t>>4][t&15] = knn[(size_t)(n0 + (t>>4))*KNB + (t&15)];
    __syncthreads();
    int nl = t / TPN; int c4 = t % TPN;
    int gi = n0 + nl;
    int base = (gi >> 13) * NN;
    const float4* pre = (const float4*)g_pre1;
    float4 sc = ((const float4*)g_bn1)[c4];
    float4 sh = ((const float4*)g_bn1)[TPN + c4];
    float4 p = pre[(size_t)gi*TPN + c4];
    float ax = fmaxf(fmaf(p.x, sc.x, sh.x), 0.f);
    float ay = fmaxf(fmaf(p.y, sc.y, sh.y), 0.f);
    float az = fmaxf(fmaf(p.z, sc.z, sh.z), 0.f);
    float aw = fmaxf(fmaf(p.w, sc.w, sh.w), 0.f);
    #pragma unroll
    for (int k=0;k<KNB;k++){
        int nb = base + sidx[nl][k];
        float4 q = pre[(size_t)nb*TPN + c4];
        ax += fmaxf(fmaf(q.x, sc.x, sh.x), 0.f);
        ay += fmaxf(fmaf(q.y, sc.y, sh.y), 0.f);
        az += fmaxf(fmaf(q.z, sc.z, sh.z), 0.f);
        aw += fmaxf(fmaf(q.w, sc.w, sh.w), 0.f);
    }
    const float s = 1.f/17.f;
    ax*=s; ay*=s; az*=s; aw*=s;
    __nv_bfloat162 h01 = __floats2bfloat162_rn(ax, ay);
    __nv_bfloat162 h23 = __floats2bfloat162_rn(az, aw);
    size_t o = (size_t)gi*32 + c4*2;
    g_a1hi[o]   = *(uint*)&h01;
    g_a1hi[o+1] = *(uint*)&h23;
    g_a1lo[o]   = pbf2(ax - __bfloat162float(h01.x), ay - __bfloat162float(h01.y));
    g_a1lo[o+1] = pbf2(az - __bfloat162float(h23.x), aw - __bfloat162float(h23.y));
}

// layer2 agg: BN+ReLU on the fly, /17 -> bf16 hi/lo
__global__ __launch_bounds__(256) void k_agg2(const int* __restrict__ knn){
    const int TPN = H2/4;         // 32
    const int NPB = 256/TPN;      // 8
    __shared__ int sidx[NPB][KNB];
    int t = threadIdx.x;
    int n0 = blockIdx.x*NPB;
    if (t < NPB*KNB) sidx[t>>4][t&15] = knn[(size_t)(n0 + (t>>4))*KNB + (t&15)];
    __syncthreads();
    int nl = t / TPN; int c4 = t % TPN;
    int gi = n0 + nl;
    int base = (gi >> 13) * NN;
    const float4* pre = (const float4*)g_pre2;
    float4 sc = ((const float4*)g_bn2)[c4];
    float4 sh = ((const float4*)g_bn2)[TPN + c4];
    float4 p = pre[(size_t)gi*TPN + c4];
    float ax = fmaxf(fmaf(p.x, sc.x, sh.x), 0.f);
    float ay = fmaxf(fmaf(p.y, sc.y, sh.y), 0.f);
    float az = fmaxf(fmaf(p.z, sc.z, sh.z), 0.f);
    float aw = fmaxf(fmaf(p.w, sc.w, sh.w), 0.f);
    #pragma unroll
    for (int k=0;k<KNB;k++){
        int nb = base + sidx[nl][k];
        float4 q = pre[(size_t)nb*TPN + c4];
        ax += fmaxf(fmaf(q.x, sc.x, sh.x), 0.f);
        ay += fmaxf(fmaf(q.y, sc.y, sh.y), 0.f);
        az += fmaxf(fmaf(q.z, sc.z, sh.z), 0.f);
        aw += fmaxf(fmaf(q.w, sc.w, sh.w), 0.f);
    }
    const float s = 1.f/17.f;
    ax*=s; ay*=s; az*=s; aw*=s;
    __nv_bfloat162 h01 = __floats2bfloat162_rn(ax, ay);
    __nv_bfloat162 h23 = __floats2bfloat162_rn(az, aw);
    size_t o = (size_t)gi*64 + c4*2;
    g_a2hi[o]   = *(uint*)&h01;
    g_a2hi[o+1] = *(uint*)&h23;
    g_a2lo[o]   = pbf2(ax - __bfloat162float(h01.x), ay - __bfloat162float(h01.y));
    g_a2lo[o+1] = pbf2(az - __bfloat162float(h23.x), aw - __bfloat162float(h23.y));
}

// ---------------- gemm1: mma bf16 split (128 nodes x 128 cols, K=64) ----------------
#define AH1_OFF 0u
#define AL1_OFF 18432u
#define BH1_OFF 36864u
#define BL1_OFF 55296u
#define S1SUM_OFF 73728u
#define S1SQ_OFF  74240u
#define G1_SMEM   74752

__global__ void __launch_bounds__(256) k_gemm1_mma(){
    extern __shared__ __align__(16) char sm[];
    uint sb = smem_u32(sm);
    int t = threadIdx.x, lane = t & 31, wid = t >> 5;
    int wm = wid >> 2, wn = wid & 3;
    int node0 = blockIdx.x*128;

    float* ssum = (float*)(sm + S1SUM_OFF);
    float* ssq  = (float*)(sm + S1SQ_OFF);

    {
        int row = t >> 1, half = t & 1;
        const uint4* ph = (const uint4*)(g_a1hi + (size_t)(node0+row)*32) + half*4;
        const uint4* pl = (const uint4*)(g_a1lo + (size_t)(node0+row)*32) + half*4;
        uint4* dh = (uint4*)(sm + AH1_OFF + row*144 + half*64);
        uint4* dl = (uint4*)(sm + AL1_OFF + row*144 + half*64);
        #pragma unroll
        for (int i=0;i<4;i++){ dh[i] = ph[i]; dl[i] = pl[i]; }
    }
    {
        int col = t >> 1, half = t & 1;
        const uint4* ph = (const uint4*)((const char*)g_w1hi + (size_t)col*128) + half*4;
        const uint4* pl = (const uint4*)((const char*)g_w1lo + (size_t)col*128) + half*4;
        uint4* dh = (uint4*)(sm + BH1_OFF + col*144 + half*64);
        uint4* dl = (uint4*)(sm + BL1_OFF + col*144 + half*64);
        #pragma unroll
        for (int i=0;i<4;i++){ dh[i] = ph[i]; dl[i] = pl[i]; }
    }
    if (t < 128){ ssum[t]=0.f; ssq[t]=0.f; }
    __syncthreads();

    uint aBase = sb + AH1_OFF + (uint)((wm*64 + (lane & 15))*144 + (lane >> 4)*16);
    uint bBase = sb + BH1_OFF + (uint)((wn*32 + (lane & 7) + ((lane >> 4) & 1)*8)*144 + ((lane >> 3) & 1)*16);

    float acc[4][4][4];
    #pragma unroll
    for (int mi=0;mi<4;mi++)
        #pragma unroll
        for (int j=0;j<4;j++)
            #pragma unroll
            for (int r=0;r<4;r++) acc[mi][j][r] = 0.f;

    #pragma unroll
    for (int ks=0; ks<4; ks++){
        uint bh[8], bl[8];
        ldm4(bh,   bBase + ks*32);
        ldm4(bh+4, bBase + 16*144 + ks*32);
        ldm4(bl,   bBase + (BL1_OFF-BH1_OFF) + ks*32);
        ldm4(bl+4, bBase + (BL1_OFF-BH1_OFF) + 16*144 + ks*32);
        #pragma unroll
        for (int mi=0; mi<4; mi++){
            uint ah[4], al[4];
            ldm4(ah, aBase + mi*16*144 + ks*32);
            ldm4(al, aBase + (AL1_OFF-AH1_OFF) + mi*16*144 + ks*32);
            #pragma unroll
            for (int j=0;j<4;j++){
                mma16816(acc[mi][j], ah, bh[2*j], bh[2*j+1]);
                mma16816(acc[mi][j], al, bh[2*j], bh[2*j+1]);
                mma16816(acc[mi][j], ah, bl[2*j], bl[2*j+1]);
            }
        }
    }

    #pragma unroll
    for (int mi=0;mi<4;mi++){
        int r0 = node0 + wm*64 + mi*16 + (lane >> 2);
        #pragma unroll
        for (int j=0;j<4;j++){
            int c0 = wn*32 + j*8 + (lane & 3)*2;
            *(float2*)&g_pre2[(size_t)r0*H2 + c0]     = make_float2(acc[mi][j][0], acc[mi][j][1]);
            *(float2*)&g_pre2[(size_t)(r0+8)*H2 + c0] = make_float2(acc[mi][j][2], acc[mi][j][3]);
        }
    }
    #pragma unroll
    for (int j=0;j<4;j++){
        #pragma unroll
        for (int p=0;p<2;p++){
            float s=0.f, qq=0.f;
            #pragma unroll
            for (int mi=0;mi<4;mi++){
                #pragma unroll
                for (int r=0;r<2;r++){
                    float v = acc[mi][j][2*r+p];
                    s += v; qq = fmaf(v, v, qq);
                }
            }
            #pragma unroll
            for (int o=4;o<32;o<<=1){
                s  += __shfl_xor_sync(0xffffffffu, s, o);
                qq += __shfl_xor_sync(0xffffffffu, qq, o);
            }
            if (lane < 4){
                int colq = wn*32 + j*8 + lane*2 + p;
                atomicAdd(&ssum[colq], s);
                atomicAdd(&ssq[colq], qq);
            }
        }
    }
    __syncthreads();
    if (t < 128){
        atomicAdd(&g_sum2[t], ssum[t]);
        atomicAdd(&g_sq2[t], ssq[t]);
    }
}

// ---------------- gemm2: mma bf16 split, K-split B (two 64-K chunks) -> 108.5KB smem, 2 CTAs/SM ----------------
#define AH_OFF 0u
#define AL_OFF 34816u
#define B2H_OFF 69632u
#define B2L_OFF 88064u
#define SSUM_OFF 106496u
#define SSQ_OFF  107008u
#define SMX_OFF  107520u
#define SMN_OFF  108032u
#define G2_SMEM  108544

__global__ void __launch_bounds__(256, 2) k_gemm2_mma(){
    extern __shared__ __align__(16) char sm[];
    uint sb = smem_u32(sm);
    int t = threadIdx.x, lane = t & 31, wid = t >> 5;
    int wm = wid >> 2, wn = wid & 3;
    int node0 = blockIdx.x*128;
    int batch = blockIdx.x >> 6;

    float* ssum = (float*)(sm + SSUM_OFF);
    float* ssq  = (float*)(sm + SSQ_OFF);
    uint*  smx  = (uint*)(sm + SMX_OFF);
    uint*  smn  = (uint*)(sm + SMN_OFF);

    // A hi/lo full K: 128 rows x 256B, stride 272
    {
        int row = t >> 1, half = t & 1;
        const uint4* ph = (const uint4*)(g_a2hi + (size_t)(node0+row)*64) + half*8;
        const uint4* pl = (const uint4*)(g_a2lo + (size_t)(node0+row)*64) + half*8;
        uint4* dh = (uint4*)(sm + AH_OFF + row*272 + half*128);
        uint4* dl = (uint4*)(sm + AL_OFF + row*272 + half*128);
        #pragma unroll
        for (int i=0;i<8;i++){ dh[i] = ph[i]; dl[i] = pl[i]; }
    }

    uint aBase = sb + AH_OFF + (uint)((wm*64 + (lane & 15))*272 + (lane >> 4)*16);
    uint bBase = sb + B2H_OFF + (uint)((wn*32 + (lane & 7) + ((lane >> 4) & 1)*8)*144 + ((lane >> 3) & 1)*16);

    for (int q = 0; q < 4; q++){
        int cb = q*128;
        if (t < 128){ ssum[t]=0.f; ssq[t]=0.f; smx[t]=0u; smn[t]=0xFFFFFFFFu; }

        float acc[4][4][4];
        #pragma unroll
        for (int mi=0;mi<4;mi++)
            #pragma unroll
            for (int j=0;j<4;j++)
                #pragma unroll
                for (int r=0;r<4;r++) acc[mi][j][r] = 0.f;

        #pragma unroll
        for (int kc=0; kc<2; kc++){
            // load B chunk: 128 cols x 64 k (128B/row, stride 144), hi+lo
            {
                int col = t >> 1, half = t & 1;
                const uint4* ph = (const uint4*)((const char*)g_w2hi + (size_t)(cb+col)*256 + kc*128) + half*4;
                const uint4* pl = (const uint4*)((const char*)g_w2lo + (size_t)(cb+col)*256 + kc*128) + half*4;
                uint4* dh = (uint4*)(sm + B2H_OFF + col*144 + half*64);
                uint4* dl = (uint4*)(sm + B2L_OFF + col*144 + half*64);
                #pragma unroll
                for (int i=0;i<4;i++){ dh[i] = ph[i]; dl[i] = pl[i]; }
            }
            __syncthreads();

            #pragma unroll
            for (int ks=0; ks<4; ks++){
                uint bh[8], bl[8];
                ldm4(bh,   bBase + ks*32);
                ldm4(bh+4, bBase + 16*144 + ks*32);
                ldm4(bl,   bBase + (B2L_OFF-B2H_OFF) + ks*32);
                ldm4(bl+4, bBase + (B2L_OFF-B2H_OFF) + 16*144 + ks*32);
                uint ak = aBase + kc*128 + ks*32;
                #pragma unroll
                for (int mi=0; mi<4; mi++){
                    uint ah[4], al[4];
                    ldm4(ah, ak + mi*16*272);
                    ldm4(al, ak + (AL_OFF-AH_OFF) + mi*16*272);
                    #pragma unroll
                    for (int j=0;j<4;j++){
                        mma16816(acc[mi][j], ah, bh[2*j], bh[2*j+1]);
                        mma16816(acc[mi][j], al, bh[2*j], bh[2*j+1]);
                        mma16816(acc[mi][j], ah, bl[2*j], bl[2*j+1]);
                    }
                }
            }
            __syncthreads();
        }

        // per-column stats
        #pragma unroll
        for (int j=0;j<4;j++){
            #pragma unroll
            for (int p=0;p<2;p++){
                float s=0.f, qq=0.f, mx=-3.402823466e38f, mn=3.402823466e38f;
                #pragma unroll
                for (int mi=0;mi<4;mi++){
                    #pragma unroll
                    for (int r=0;r<2;r++){
                        float v = acc[mi][j][2*r+p];
                        s += v; qq = fmaf(v, v, qq);
                        mx = fmaxf(mx, v); mn = fminf(mn, v);
                    }
                }
                #pragma unroll
                for (int o=4;o<32;o<<=1){
                    s  += __shfl_xor_sync(0xffffffffu, s, o);
                    qq += __shfl_xor_sync(0xffffffffu, qq, o);
                    mx = fmaxf(mx, __shfl_xor_sync(0xffffffffu, mx, o));
                    mn = fminf(mn, __shfl_xor_sync(0xffffffffu, mn, o));
                }
                if (lane < 4){
                    int colq = wn*32 + j*8 + lane*2 + p;
                    atomicAdd(&ssum[colq], s);
                    atomicAdd(&ssq[colq], qq);
                    atomicMax(&smx[colq], fkey(mx));
                    atomicMin(&smn[colq], fkey(mn));
                }
            }
        }
        __syncthreads();
        if (t < 128){
            atomicAdd(&g_sum3[cb+t], ssum[t]);
            atomicAdd(&g_sq3[cb+t], ssq[t]);
            atomicMax(&g_maxk[batch*H1 + cb + t], smx[t]);
            atomicMin(&g_mink[batch*H1 + cb + t], smn[t]);
        }
        __syncthreads();
    }
}

// e2 linear fused with BN3-pool: block per batch
__global__ __launch_bounds__(512) void k_e2(
    const float* __restrict__ g, const float* __restrict__ be,
    const float* __restrict__ W, const float* __restrict__ bias)
{
    __shared__ float sp[H1];
    int b = blockIdx.x, c = threadIdx.x;
    {
        float invM = 1.f/(float)MTOT;
        float s = g_sum3[c]*invM;
        float q = g_sq3[c]*invM;
        float v = fmaxf(q - s*s, 0.f);
        float sc = g[c]*rsqrtf(v+EPSBN);
        float sh = fmaf(-s, sc, be[c]);
        float mx = keyf(g_maxk[b*H1+c]);
        float mn = keyf(g_mink[b*H1+c]);
        float val = (sc >= 0.f) ? fmaf(mx, sc, sh) : fmaf(mn, sc, sh);
        sp[c] = fmaxf(val, 0.f);
    }
    __syncthreads();
    float acc = bias[c];
    #pragma unroll 4
    for (int f=0; f<H1; f++) acc = fmaf(sp[f], W[(size_t)f*H1 + c], acc);
    g_pre4[b*H1 + c] = acc;
}

// e2 BN(M=16)+ReLU -> code; decoder per-batch dots; analytic d1 BN params
__global__ __launch_bounds__(512) void k_code2(
    const float* __restrict__ eg, const float* __restrict__ ebe,
    const float* __restrict__ d1w, const float* __restrict__ d1b,
    const float* __restrict__ d1g, const float* __restrict__ d1be,
    const float* __restrict__ d2w, const float* __restrict__ d2b)
{
    __shared__ float scm[BB*H1];
    int t = threadIdx.x;
    float vals[16]; float s = 0.f;
    #pragma unroll
    for (int b=0;b<16;b++){ vals[b]=g_pre4[b*H1+t]; s+=vals[b]; }
    float m = s*(1.f/16.f);
    float q = 0.f;
    #pragma unroll
    for (int b=0;b<16;b++){ float d=vals[b]-m; q+=d*d; }
    float scl = eg[t]*rsqrtf(q*(1.f/16.f)+EPSBN);
    float sh = ebe[t];
    #pragma unroll
    for (int b=0;b<16;b++) scm[b*H1+t] = fmaxf(fmaf(vals[b]-m, scl, sh), 0.f);
    __syncthreads();

    int w = t>>5, lane = t&31;
    if (w < 6){
        for (int d = w*16; d < w*16+16; d++){
            int layer = d/48; int r = d%48; int b = r/3; int c = r%3;
            const float* Wd = layer ? d2w : d1w;
            float p = 0.f;
            for (int f=lane; f<H1; f+=32) p = fmaf(scm[b*H1+f], Wd[f*3+c], p);
            #pragma unroll
            for (int o=16;o;o>>=1) p += __shfl_xor_sync(0xffffffffu, p, o);
            if (lane==0){
                if (layer) g_dc2[b*3+c] = p + d2b[c];
                else       g_dc1[b*3+c] = p + d1b[c];
            }
        }
    }
    __syncthreads();
    if (w < 3){
        float wx = d1w[1536 + w], wy = d1w[1539 + w];
        float sG = 0.f;
        for (int n=lane; n<NN; n+=32){
            int ix = n/65, iy = n - ix*65;
            float gx = 1.f + ix*(119.f/128.f);
            float gy = 1.f + iy*(59.f/64.f);
            sG += gx*wx + gy*wy;
        }
        #pragma unroll
        for (int o=16;o;o>>=1) sG += __shfl_xor_sync(0xffffffffu, sG, o);
        float mG = sG*(1.f/8192.f);
        float qG = 0.f;
        for (int n=lane; n<NN; n+=32){
            int ix = n/65, iy = n - ix*65;
            float gx = 1.f + ix*(119.f/128.f);
            float gy = 1.f + iy*(59.f/64.f);
            float d = gx*wx + gy*wy - mG;
            qG += d*d;
        }
        #pragma unroll
        for (int o=16;o;o>>=1) qG += __shfl_xor_sync(0xffffffffu, qG, o);
        if (lane==0){
            float vG = qG*(1.f/8192.f);
            float sA=0.f;
            #pragma unroll
            for (int b=0;b<16;b++) sA += g_dc1[b*3+w];
            float mA = sA*(1.f/16.f);
            float qA=0.f;
            #pragma unroll
            for (int b=0;b<16;b++){ float d=g_dc1[b*3+w]-mA; qA+=d*d; }
            float vA = qA*(1.f/16.f);
            float mean = mA + mG;
            float var = fmaxf(vA + vG, 0.f);
            float sc1 = d1g[w]*rsqrtf(var+EPSBN);
            g_d1p[w]=sc1; g_d1p[3+w]= d1be[w] - mean*sc1;
        }
    }
}

// decode stats only
__global__ __launch_bounds__(256) void k_decode(const float* __restrict__ d1w, const float* __restrict__ d2w){
    __shared__ float ss[3], sq_[3];
    int t = threadIdx.x;
    if (t<3){ ss[t]=0.f; sq_[t]=0.f; }
    __syncthreads();
    int gi = blockIdx.x*256 + t;
    int n = gi & (NN-1);
    int b = gi >> 13;
    int ix = n/65, iy = n - ix*65;
    float gx = 1.f + ix*(119.f/128.f);
    float gy = 1.f + iy*(59.f/64.f);
    float z1[3];
    #pragma unroll
    for (int c=0;c<3;c++){
        float pre = g_dc1[b*3+c] + gx*d1w[1536+c] + gy*d1w[1539+c];
        z1[c] = fmaxf(fmaf(pre, g_d1p[c], g_d1p[3+c]), 0.f);
    }
    int lane = t & 31;
    #pragma unroll
    for (int c=0;c<3;c++){
        float v = g_dc2[b*3+c] + z1[0]*d2w[1536+c] + z1[1]*d2w[1539+c] + z1[2]*d2w[1542+c];
        float sv = v, qv = v*v;
        #pragma unroll
        for (int o=16;o;o>>=1){ sv += __shfl_xor_sync(0xffffffffu, sv, o); qv += __shfl_xor_sync(0xffffffffu, qv, o); }
        if (lane==0){ atomicAdd(&ss[c], sv); atomicAdd(&sq_[c], qv); }
    }
    __syncthreads();
    if (t<3){ atomicAdd(&g_sumd[t], ss[t]); atomicAdd(&g_sqd[t], sq_[t]); }
}

// out: recompute decoder output analytically + final BN+ReLU
__global__ __launch_bounds__(256) void k_out(
    float* __restrict__ out, const float* __restrict__ d1w, const float* __restrict__ d2w,
    const float* __restrict__ g, const float* __restrict__ be)
{
    int gi = blockIdx.x*256 + threadIdx.x;
    int n = gi & (NN-1);
    int b = gi >> 13;
    int ix = n/65, iy = n - ix*65;
    float gx = 1.f + ix*(119.f/128.f);
    float gy = 1.f + iy*(59.f/64.f);
    float z1[3];
    #pragma unroll
    for (int c=0;c<3;c++){
        float pre = g_dc1[b*3+c] + gx*d1w[1536+c] + gy*d1w[1539+c];
        z1[c] = fmaxf(fmaf(pre, g_d1p[c], g_d1p[3+c]), 0.f);
    }
    float invM = 1.f/(float)MTOT;
    #pragma unroll
    for (int c=0;c<3;c++){
        float v = g_dc2[b*3+c] + z1[0]*d2w[1536+c] + z1[1]*d2w[1539+c] + z1[2]*d2w[1542+c];
        float m = g_sumd[c]*invM;
        float var = fmaxf(g_sqd[c]*invM - m*m, 0.f);
        float sc = g[c]*rsqrtf(var+EPSBN);
        out[(size_t)gi*3 + c] = fmaxf(fmaf(v-m, sc, be[c]), 0.f);
    }
}

// ---------------- launch ----------------
extern "C" void kernel_launch(void* const* d_in, const int* in_sizes, int n_in,
                              void* d_out, int out_size)
{
    const float* data = (const float*)d_in[0];
    const int*   knn  = (const int*)  d_in[1];
    const float* e1w  = (const float*)d_in[2];
    const float* e1b  = (const float*)d_in[3];
    const float* e1g  = (const float*)d_in[4];
    const float* e1be = (const float*)d_in[5];
    const float* gc1w = (const float*)d_in[6];
    const float* g1g  = (const float*)d_in[8];
    const float* g1be = (const float*)d_in[9];
    const float* gc2w = (const float*)d_in[10];
    const float* g2g  = (const float*)d_in[12];
    const float* g2be = (const float*)d_in[13];
    const float* e2w  = (const float*)d_in[14];
    const float* e2b  = (const float*)d_in[15];
    const float* e2g  = (const float*)d_in[16];
    const float* e2be = (const float*)d_in[17];
    const float* d1w  = (const float*)d_in[18];
    const float* d1b  = (const float*)d_in[19];
    const float* d1g  = (const float*)d_in[20];
    const float* d1be = (const float*)d_in[21];
    const float* d2w  = (const float*)d_in[22];
    const float* d2b  = (const float*)d_in[23];
    const float* d2g  = (const float*)d_in[24];
    const float* d2be = (const float*)d_in[25];
    float* out = (float*)d_out;

    cudaFuncSetAttribute(k_gemm1_mma, cudaFuncAttributeMaxDynamicSharedMemorySize, G1_SMEM);
    cudaFuncSetAttribute(k_gemm2_mma, cudaFuncAttributeMaxDynamicSharedMemorySize, G2_SMEM);

    k_init<<<256, 256>>>(gc1w, gc2w);
    k_cov_e1<<<MTOT/256, 256>>>(data, knn, e1w, e1b);
    k_fin<H3,1><<<1, H3>>>(e1g, e1be);
    k_agg1<<<MTOT/16, 256>>>(knn);
    k_gemm1_mma<<<MTOT/128, 256, G1_SMEM>>>();
    k_fin<H2,2><<<1, H2>>>(g1g, g1be);
    k_agg2<<<MTOT/8, 256>>>(knn);
    k_gemm2_mma<<<MTOT/128, 256, G2_SMEM>>>();
    k_e2<<<BB, H1>>>(g2g, g2be, e2w, e2b);
    k_code2<<<1, 512>>>(e2g, e2be, d1w, d1b, d1g, d1be, d2w, d2b);
    k_decode<<<MTOT/256, 256>>>(d1w, d2w);
    k_out<<<MTOT/256, 256>>>(out, d1w, d2w, d2g, d2be);
}